// round 1
// baseline (speedup 1.0000x reference)
#include <cuda_runtime.h>
#include <math.h>

#define Bsz 2
#define Sq 2048
#define DM 1024
#define Hh 16
#define HDv 64
#define Mrows (Bsz*Sq)   /* 4096 */

// Scratch (device globals — no allocations allowed)
__device__ float g_Q[Mrows*DM];
__device__ float g_K[Mrows*DM];
__device__ float g_V[Mrows*DM];
__device__ float g_C[Mrows*DM];

// ---------------------------------------------------------------------------
// Tiled SGEMM: C[M,N] = A[M,K] @ B[K,N] (+ bias). BM=BN=128, BK=16,
// 256 threads, 8x8 micro-tile per thread.
// ---------------------------------------------------------------------------
template<bool HAS_BIAS>
__global__ __launch_bounds__(256) void sgemm_kernel(
    const float* __restrict__ A, const float* __restrict__ B,
    const float* __restrict__ bias, float* __restrict__ C,
    int M, int N, int K)
{
    __shared__ __align__(16) float As[16][128];
    __shared__ __align__(16) float Bs[16][128];
    const int tid = threadIdx.x;
    const int tx = tid & 15;
    const int ty = tid >> 4;
    const int rowBase = blockIdx.y * 128;
    const int colBase = blockIdx.x * 128;

    float acc[8][8];
#pragma unroll
    for (int i = 0; i < 8; i++)
#pragma unroll
        for (int j = 0; j < 8; j++) acc[i][j] = 0.f;

    for (int k0 = 0; k0 < K; k0 += 16) {
        // Load A tile (128 rows x 16 k) -> As[k][row]
#pragma unroll
        for (int l = 0; l < 2; l++) {
            int f = l * 256 + tid;          // 0..511 float4s
            int r = f >> 2, c4 = f & 3;
            float4 v = *(const float4*)(A + (size_t)(rowBase + r) * K + k0 + c4 * 4);
            As[c4 * 4 + 0][r] = v.x;
            As[c4 * 4 + 1][r] = v.y;
            As[c4 * 4 + 2][r] = v.z;
            As[c4 * 4 + 3][r] = v.w;
        }
        // Load B tile (16 k x 128 cols) -> Bs[k][col]
#pragma unroll
        for (int l = 0; l < 2; l++) {
            int f = l * 256 + tid;
            int r = f >> 5, c4 = f & 31;
            *(float4*)&Bs[r][c4 * 4] =
                *(const float4*)(B + (size_t)(k0 + r) * N + colBase + c4 * 4);
        }
        __syncthreads();

#pragma unroll
        for (int kk = 0; kk < 16; kk++) {
            float a[8], bb[8];
#pragma unroll
            for (int i = 0; i < 8; i++) a[i] = As[kk][ty * 8 + i];
#pragma unroll
            for (int j = 0; j < 8; j++) bb[j] = Bs[kk][tx * 8 + j];
#pragma unroll
            for (int i = 0; i < 8; i++)
#pragma unroll
                for (int j = 0; j < 8; j++)
                    acc[i][j] += a[i] * bb[j];
        }
        __syncthreads();
    }

#pragma unroll
    for (int i = 0; i < 8; i++) {
        int r = rowBase + ty * 8 + i;
#pragma unroll
        for (int j = 0; j < 8; j += 4) {
            int c = colBase + tx * 8 + j;
            float4 v = make_float4(acc[i][j], acc[i][j + 1], acc[i][j + 2], acc[i][j + 3]);
            if (HAS_BIAS) {
                v.x += bias[c]; v.y += bias[c + 1]; v.z += bias[c + 2]; v.w += bias[c + 3];
            }
            *(float4*)(C + (size_t)r * N + c) = v;
        }
    }
}

// ---------------------------------------------------------------------------
// Causal flash attention, fp32. One thread = one query row (HD=64 acc in regs).
// Block = 64 queries. K/V/S tiles transposed in SMEM: Ks[d][j], Vs[d][j]
// (conflict-free column writes, float4 broadcast reads), Ss[j][tid].
// Online softmax in exp2 domain; q pre-scaled by (1/sqrt(HD))*log2(e).
// ---------------------------------------------------------------------------
__global__ __launch_bounds__(64) void attn_kernel(
    const float* __restrict__ Q, const float* __restrict__ K,
    const float* __restrict__ V, float* __restrict__ O)
{
    __shared__ __align__(16) float Ks[HDv][64];
    __shared__ __align__(16) float Vs[HDv][64];
    __shared__ __align__(16) float Ss[64][64];

    const int mblk = gridDim.x - 1 - blockIdx.x;  // heavy blocks first
    const int bh = blockIdx.y;
    const int b = bh >> 4;        // / Hh
    const int h = bh & 15;        // % Hh
    const int tid = threadIdx.x;
    const float scale = 0.125f * 1.44269504088896340736f; // 1/sqrt(64) * log2(e)

    const int qtok = mblk * 64 + tid;
    const float* qptr = Q + (size_t)(b * Sq + qtok) * DM + h * HDv;

    float q[HDv];
#pragma unroll
    for (int d4 = 0; d4 < HDv / 4; d4++) {
        float4 t = *(const float4*)(qptr + d4 * 4);
        q[d4 * 4 + 0] = t.x * scale;
        q[d4 * 4 + 1] = t.y * scale;
        q[d4 * 4 + 2] = t.z * scale;
        q[d4 * 4 + 3] = t.w * scale;
    }
    float acc[HDv];
#pragma unroll
    for (int d = 0; d < HDv; d++) acc[d] = 0.f;
    float m = -INFINITY, l = 0.f;

    for (int t = 0; t <= mblk; t++) {
        const int ktok = t * 64 + tid;
        const float* kp = K + (size_t)(b * Sq + ktok) * DM + h * HDv;
        const float* vp = V + (size_t)(b * Sq + ktok) * DM + h * HDv;
#pragma unroll
        for (int d4 = 0; d4 < HDv / 4; d4++) {
            float4 kv = *(const float4*)(kp + d4 * 4);
            Ks[d4 * 4 + 0][tid] = kv.x;
            Ks[d4 * 4 + 1][tid] = kv.y;
            Ks[d4 * 4 + 2][tid] = kv.z;
            Ks[d4 * 4 + 3][tid] = kv.w;
            float4 vv = *(const float4*)(vp + d4 * 4);
            Vs[d4 * 4 + 0][tid] = vv.x;
            Vs[d4 * 4 + 1][tid] = vv.y;
            Vs[d4 * 4 + 2][tid] = vv.z;
            Vs[d4 * 4 + 3][tid] = vv.w;
        }
        __syncthreads();

        const int jmax = (t == mblk) ? (tid + 1) : 64;
        float mt = m;
        for (int j = 0; j < 64; j += 4) {
            float s0 = 0.f, s1 = 0.f, s2 = 0.f, s3 = 0.f;
#pragma unroll
            for (int d = 0; d < HDv; d++) {
                float4 kk = *(const float4*)&Ks[d][j];
                s0 += q[d] * kk.x;
                s1 += q[d] * kk.y;
                s2 += q[d] * kk.z;
                s3 += q[d] * kk.w;
            }
            if (j + 0 >= jmax) s0 = -INFINITY;
            if (j + 1 >= jmax) s1 = -INFINITY;
            if (j + 2 >= jmax) s2 = -INFINITY;
            if (j + 3 >= jmax) s3 = -INFINITY;
            Ss[j + 0][tid] = s0;
            Ss[j + 1][tid] = s1;
            Ss[j + 2][tid] = s2;
            Ss[j + 3][tid] = s3;
            mt = fmaxf(mt, fmaxf(fmaxf(s0, s1), fmaxf(s2, s3)));
        }

        const float alpha = exp2f(m - mt);
        m = mt;
        l *= alpha;
#pragma unroll
        for (int d = 0; d < HDv; d++) acc[d] *= alpha;

        for (int j = 0; j < 64; j += 4) {
            float p0 = exp2f(Ss[j + 0][tid] - m);
            float p1 = exp2f(Ss[j + 1][tid] - m);
            float p2 = exp2f(Ss[j + 2][tid] - m);
            float p3 = exp2f(Ss[j + 3][tid] - m);
            l += (p0 + p1) + (p2 + p3);
#pragma unroll
            for (int d = 0; d < HDv; d++) {
                float4 vv = *(const float4*)&Vs[d][j];
                acc[d] += p0 * vv.x;
                acc[d] += p1 * vv.y;
                acc[d] += p2 * vv.z;
                acc[d] += p3 * vv.w;
            }
        }
        __syncthreads();
    }

    const float inv = 1.f / l;
    float* op = O + (size_t)(b * Sq + qtok) * DM + h * HDv;
#pragma unroll
    for (int d4 = 0; d4 < HDv / 4; d4++) {
        float4 o;
        o.x = acc[d4 * 4 + 0] * inv;
        o.y = acc[d4 * 4 + 1] * inv;
        o.z = acc[d4 * 4 + 2] * inv;
        o.w = acc[d4 * 4 + 3] * inv;
        *(float4*)(op + d4 * 4) = o;
    }
}

// ---------------------------------------------------------------------------
extern "C" void kernel_launch(void* const* d_in, const int* in_sizes, int n_in,
                              void* d_out, int out_size)
{
    const float* x  = (const float*)d_in[0];
    const float* Wq = (const float*)d_in[1];
    const float* Wk = (const float*)d_in[2];
    const float* Wv = (const float*)d_in[3];
    const float* Wo = (const float*)d_in[4];
    const float* bo = (const float*)d_in[5];
    float* out = (float*)d_out;

    float *Qp, *Kp, *Vp, *Cp;
    cudaGetSymbolAddress((void**)&Qp, g_Q);
    cudaGetSymbolAddress((void**)&Kp, g_K);
    cudaGetSymbolAddress((void**)&Vp, g_V);
    cudaGetSymbolAddress((void**)&Cp, g_C);

    dim3 gg(DM / 128, Mrows / 128);
    dim3 gb(256);
    sgemm_kernel<false><<<gg, gb>>>(x, Wq, nullptr, Qp, Mrows, DM, DM);
    sgemm_kernel<false><<<gg, gb>>>(x, Wk, nullptr, Kp, Mrows, DM, DM);
    sgemm_kernel<false><<<gg, gb>>>(x, Wv, nullptr, Vp, Mrows, DM, DM);

    dim3 ga(Sq / 64, Bsz * Hh);
    attn_kernel<<<ga, 64>>>(Qp, Kp, Vp, Cp);

    sgemm_kernel<true><<<gg, gb>>>(Cp, Wo, bo, out, Mrows, DM, DM);
}

// round 2
// speedup vs baseline: 1.2199x; 1.2199x over previous
#include <cuda_runtime.h>
#include <math.h>

#define Bsz 2
#define Sq 2048
#define DM 1024
#define Hh 16
#define HDv 64
#define Mrows (Bsz*Sq)   /* 4096 */

#define BR 128
#define BC 64

// Scratch (device globals — no allocations allowed)
__device__ float g_Q[Mrows*DM];
__device__ float g_K[Mrows*DM];
__device__ float g_V[Mrows*DM];
__device__ float g_C[Mrows*DM];

// ---------------------------------------------------------------------------
// Tiled SGEMM: C[M,N] = A[M,K] @ B[K,N] (+ bias). BM=BN=128, BK=16,
// 256 threads, 8x8 micro-tile per thread. (~at fp32 FFMA roofline)
// ---------------------------------------------------------------------------
template<bool HAS_BIAS>
__global__ __launch_bounds__(256) void sgemm_kernel(
    const float* __restrict__ A, const float* __restrict__ B,
    const float* __restrict__ bias, float* __restrict__ C,
    int M, int N, int K)
{
    __shared__ __align__(16) float As[16][128];
    __shared__ __align__(16) float Bs[16][128];
    const int tid = threadIdx.x;
    const int tx = tid & 15;
    const int ty = tid >> 4;
    const int rowBase = blockIdx.y * 128;
    const int colBase = blockIdx.x * 128;

    float acc[8][8];
#pragma unroll
    for (int i = 0; i < 8; i++)
#pragma unroll
        for (int j = 0; j < 8; j++) acc[i][j] = 0.f;

    for (int k0 = 0; k0 < K; k0 += 16) {
#pragma unroll
        for (int l = 0; l < 2; l++) {
            int f = l * 256 + tid;
            int r = f >> 2, c4 = f & 3;
            float4 v = *(const float4*)(A + (size_t)(rowBase + r) * K + k0 + c4 * 4);
            As[c4 * 4 + 0][r] = v.x;
            As[c4 * 4 + 1][r] = v.y;
            As[c4 * 4 + 2][r] = v.z;
            As[c4 * 4 + 3][r] = v.w;
        }
#pragma unroll
        for (int l = 0; l < 2; l++) {
            int f = l * 256 + tid;
            int r = f >> 5, c4 = f & 31;
            *(float4*)&Bs[r][c4 * 4] =
                *(const float4*)(B + (size_t)(k0 + r) * N + colBase + c4 * 4);
        }
        __syncthreads();

#pragma unroll
        for (int kk = 0; kk < 16; kk++) {
            float a[8], bb[8];
#pragma unroll
            for (int i = 0; i < 8; i++) a[i] = As[kk][ty * 8 + i];
#pragma unroll
            for (int j = 0; j < 8; j++) bb[j] = Bs[kk][tx * 8 + j];
#pragma unroll
            for (int i = 0; i < 8; i++)
#pragma unroll
                for (int j = 0; j < 8; j++)
                    acc[i][j] += a[i] * bb[j];
        }
        __syncthreads();
    }

#pragma unroll
    for (int i = 0; i < 8; i++) {
        int r = rowBase + ty * 8 + i;
#pragma unroll
        for (int j = 0; j < 8; j += 4) {
            int c = colBase + tx * 8 + j;
            float4 v = make_float4(acc[i][j], acc[i][j + 1], acc[i][j + 2], acc[i][j + 3]);
            if (HAS_BIAS) {
                v.x += bias[c]; v.y += bias[c + 1]; v.z += bias[c + 2]; v.w += bias[c + 3];
            }
            *(float4*)(C + (size_t)r * N + c) = v;
        }
    }
}

// ---------------------------------------------------------------------------
// Register-tiled causal flash attention, fp32.
// Block: 256 threads, Br=128 queries, Bc=64 keys/tile, one (b,h) per block.y.
// Thread (tx,ty): tx=tid&15 (4 key-cols), ty=tid>>4 (8 q-rows).
// SMEM (dynamic, 100KB): Qs[64][132] k-major (loaded once, pre-scaled),
// Kt[64][68] k-major, Vs[64][68] row-major, Ps[64][132] k-major.
// All GEMM fragment reads are warp-broadcast float4 (conflict-free).
// Online softmax in exp2 domain; row reductions via 4 butterfly shuffles.
// ---------------------------------------------------------------------------
__global__ __launch_bounds__(256) void attn_kernel(
    const float* __restrict__ Q, const float* __restrict__ K,
    const float* __restrict__ V, float* __restrict__ O)
{
    extern __shared__ __align__(16) float sm[];
    float* Qs = sm;             // 64*132 = 8448
    float* Kt = sm + 8448;      // 64*68  = 4352
    float* Vs = sm + 12800;     // 64*68  = 4352
    float* Ps = sm + 17152;     // 64*132 = 8448  (total 25600 floats = 100KB)

    const int mblk = (int)gridDim.x - 1 - (int)blockIdx.x;  // heavy-first
    const int bh = blockIdx.y;
    const int b = bh >> 4;
    const int h = bh & 15;
    const int tid = threadIdx.x;
    const int tx = tid & 15;
    const int ty = tid >> 4;
    const float scale = 0.125f * 1.44269504088896340736f; // 1/sqrt(64)*log2(e)

    // ---- Load Q tile transposed+scaled: Qs[d][row] ----
    const float* qbase = Q + ((size_t)(b * Sq + mblk * BR)) * DM + h * HDv;
    for (int idx = tid; idx < BR * 16; idx += 256) {
        int row = idx >> 4;
        int d4 = (idx & 15) * 4;
        float4 v = *(const float4*)(qbase + (size_t)row * DM + d4);
        Qs[(d4 + 0) * 132 + row] = v.x * scale;
        Qs[(d4 + 1) * 132 + row] = v.y * scale;
        Qs[(d4 + 2) * 132 + row] = v.z * scale;
        Qs[(d4 + 3) * 132 + row] = v.w * scale;
    }

    float Oa[8][4];
#pragma unroll
    for (int i = 0; i < 8; i++)
#pragma unroll
        for (int j = 0; j < 4; j++) Oa[i][j] = 0.f;
    float mrow[8], lrow[8];
#pragma unroll
    for (int i = 0; i < 8; i++) { mrow[i] = -INFINITY; lrow[i] = 0.f; }

    const int ntiles = 2 * mblk + 2;

    for (int t = 0; t < ntiles; t++) {
        __syncthreads();  // protect Kt/Vs/Ps from previous iteration

        // ---- Load K tile transposed (Kt[d][key]) and V tile direct (Vs[key][d]) ----
        const float* kbase = K + ((size_t)(b * Sq + t * BC)) * DM + h * HDv;
        const float* vbase = V + ((size_t)(b * Sq + t * BC)) * DM + h * HDv;
        for (int idx = tid; idx < BC * 16; idx += 256) {
            int key = idx >> 4;
            int d4 = (idx & 15) * 4;
            float4 kv = *(const float4*)(kbase + (size_t)key * DM + d4);
            Kt[(d4 + 0) * 68 + key] = kv.x;
            Kt[(d4 + 1) * 68 + key] = kv.y;
            Kt[(d4 + 2) * 68 + key] = kv.z;
            Kt[(d4 + 3) * 68 + key] = kv.w;
            float4 vv = *(const float4*)(vbase + (size_t)key * DM + d4);
            *(float4*)&Vs[key * 68 + d4] = vv;
        }
        __syncthreads();

        // ---- S = Q @ K^T (register micro-tile 8x4) ----
        float S[8][4];
#pragma unroll
        for (int i = 0; i < 8; i++)
#pragma unroll
            for (int j = 0; j < 4; j++) S[i][j] = 0.f;

#pragma unroll 4
        for (int k = 0; k < 64; k++) {
            float4 a0 = *(const float4*)&Qs[k * 132 + ty * 8];
            float4 a1 = *(const float4*)&Qs[k * 132 + ty * 8 + 4];
            float4 bb = *(const float4*)&Kt[k * 68 + tx * 4];
            float a[8] = {a0.x, a0.y, a0.z, a0.w, a1.x, a1.y, a1.z, a1.w};
            float bj[4] = {bb.x, bb.y, bb.z, bb.w};
#pragma unroll
            for (int i = 0; i < 8; i++)
#pragma unroll
                for (int j = 0; j < 4; j++)
                    S[i][j] += a[i] * bj[j];
        }

        // ---- Causal mask (only last two tiles intersect the diagonal) ----
        if (t >= ntiles - 2) {
            const int rowg = mblk * BR + ty * 8;
            const int colg = t * BC + tx * 4;
#pragma unroll
            for (int i = 0; i < 8; i++)
#pragma unroll
                for (int j = 0; j < 4; j++)
                    if (colg + j > rowg + i) S[i][j] = -1e30f;
        }

        // ---- Online softmax: row max/sum via butterfly shuffles over tx ----
#pragma unroll
        for (int i = 0; i < 8; i++) {
            float mt = fmaxf(fmaxf(S[i][0], S[i][1]), fmaxf(S[i][2], S[i][3]));
            mt = fmaxf(mt, __shfl_xor_sync(0xffffffffu, mt, 1));
            mt = fmaxf(mt, __shfl_xor_sync(0xffffffffu, mt, 2));
            mt = fmaxf(mt, __shfl_xor_sync(0xffffffffu, mt, 4));
            mt = fmaxf(mt, __shfl_xor_sync(0xffffffffu, mt, 8));
            float mnew = fmaxf(mrow[i], mt);
            float alpha = exp2f(mrow[i] - mnew);
            mrow[i] = mnew;
            lrow[i] *= alpha;
#pragma unroll
            for (int j = 0; j < 4; j++) Oa[i][j] *= alpha;
            float p0 = exp2f(S[i][0] - mnew);
            float p1 = exp2f(S[i][1] - mnew);
            float p2 = exp2f(S[i][2] - mnew);
            float p3 = exp2f(S[i][3] - mnew);
            S[i][0] = p0; S[i][1] = p1; S[i][2] = p2; S[i][3] = p3;
            float rs = (p0 + p1) + (p2 + p3);
            rs += __shfl_xor_sync(0xffffffffu, rs, 1);
            rs += __shfl_xor_sync(0xffffffffu, rs, 2);
            rs += __shfl_xor_sync(0xffffffffu, rs, 4);
            rs += __shfl_xor_sync(0xffffffffu, rs, 8);
            lrow[i] += rs;
        }

        // ---- Store P transposed: Ps[col][row] (float4 over rows) ----
#pragma unroll
        for (int j = 0; j < 4; j++) {
            int col = tx * 4 + j;
            *(float4*)&Ps[col * 132 + ty * 8] =
                make_float4(S[0][j], S[1][j], S[2][j], S[3][j]);
            *(float4*)&Ps[col * 132 + ty * 8 + 4] =
                make_float4(S[4][j], S[5][j], S[6][j], S[7][j]);
        }
        __syncthreads();

        // ---- O += P @ V ----
#pragma unroll 4
        for (int k = 0; k < 64; k++) {
            float4 a0 = *(const float4*)&Ps[k * 132 + ty * 8];
            float4 a1 = *(const float4*)&Ps[k * 132 + ty * 8 + 4];
            float4 bb = *(const float4*)&Vs[k * 68 + tx * 4];
            float a[8] = {a0.x, a0.y, a0.z, a0.w, a1.x, a1.y, a1.z, a1.w};
            float bj[4] = {bb.x, bb.y, bb.z, bb.w};
#pragma unroll
            for (int i = 0; i < 8; i++)
#pragma unroll
                for (int j = 0; j < 4; j++)
                    Oa[i][j] += a[i] * bj[j];
        }
    }

    // ---- Epilogue: normalize + store ----
    float* obase = O + ((size_t)(b * Sq + mblk * BR)) * DM + h * HDv;
#pragma unroll
    for (int i = 0; i < 8; i++) {
        float inv = 1.f / lrow[i];
        float4 v = make_float4(Oa[i][0] * inv, Oa[i][1] * inv,
                               Oa[i][2] * inv, Oa[i][3] * inv);
        *(float4*)(obase + (size_t)(ty * 8 + i) * DM + tx * 4) = v;
    }
}

// ---------------------------------------------------------------------------
extern "C" void kernel_launch(void* const* d_in, const int* in_sizes, int n_in,
                              void* d_out, int out_size)
{
    const float* x  = (const float*)d_in[0];
    const float* Wq = (const float*)d_in[1];
    const float* Wk = (const float*)d_in[2];
    const float* Wv = (const float*)d_in[3];
    const float* Wo = (const float*)d_in[4];
    const float* bo = (const float*)d_in[5];
    float* out = (float*)d_out;

    float *Qp, *Kp, *Vp, *Cp;
    cudaGetSymbolAddress((void**)&Qp, g_Q);
    cudaGetSymbolAddress((void**)&Kp, g_K);
    cudaGetSymbolAddress((void**)&Vp, g_V);
    cudaGetSymbolAddress((void**)&Cp, g_C);

    dim3 gg(DM / 128, Mrows / 128);
    sgemm_kernel<false><<<gg, 256>>>(x, Wq, nullptr, Qp, Mrows, DM, DM);
    sgemm_kernel<false><<<gg, 256>>>(x, Wk, nullptr, Kp, Mrows, DM, DM);
    sgemm_kernel<false><<<gg, 256>>>(x, Wv, nullptr, Vp, Mrows, DM, DM);

    const int smem_bytes = 25600 * sizeof(float);  // 100 KB
    static int attr_set = 0;
    if (!attr_set) {
        cudaFuncSetAttribute(attn_kernel,
                             cudaFuncAttributeMaxDynamicSharedMemorySize, smem_bytes);
        attr_set = 1;
    }
    dim3 ga(Sq / BR, Bsz * Hh);
    attn_kernel<<<ga, 256, smem_bytes>>>(Qp, Kp, Vp, Cp);

    sgemm_kernel<true><<<gg, 256>>>(Cp, Wo, bo, out, Mrows, DM, DM);
}

// round 4
// speedup vs baseline: 1.8560x; 1.5214x over previous
#include <cuda_runtime.h>
#include <cuda_bf16.h>
#include <math.h>
#include <stdint.h>

#define Bsz 2
#define Sq 2048
#define DM 1024
#define Hh 16
#define HDv 64
#define Mrows (Bsz*Sq)   /* 4096 */

#define BR 128
#define BC 64

// ---------------- scratch (device globals; no allocs allowed) ----------------
__device__ float g_Q[Mrows*DM];
__device__ float g_K[Mrows*DM];
__device__ float g_V[Mrows*DM];
__device__ float g_C[Mrows*DM];
__device__ __nv_bfloat16 g_xh[Mrows*DM];
__device__ __nv_bfloat16 g_xl[Mrows*DM];
__device__ __nv_bfloat16 g_ch[Mrows*DM];
__device__ __nv_bfloat16 g_cl[Mrows*DM];
__device__ __nv_bfloat16 g_wth[4*DM*DM];   // W^T split-hi, [N][K], order q,k,v,o
__device__ __nv_bfloat16 g_wtl[4*DM*DM];   // W^T split-lo

// ---------------- helpers ----------------
__device__ __forceinline__ uint32_t smem_u32(const void* p) {
    uint32_t a;
    asm("{ .reg .u64 t; cvta.to.shared.u64 t, %1; cvt.u32.u64 %0, t; }" : "=r"(a) : "l"(p));
    return a;
}
__device__ __forceinline__ void ldsm4(uint32_t* r, uint32_t addr) {
    asm volatile("ldmatrix.sync.aligned.m8n8.x4.shared.b16 {%0,%1,%2,%3}, [%4];"
                 : "=r"(r[0]), "=r"(r[1]), "=r"(r[2]), "=r"(r[3]) : "r"(addr));
}
__device__ __forceinline__ void mma16816(float* c, const uint32_t* a, uint32_t b0, uint32_t b1) {
    asm volatile("mma.sync.aligned.m16n8k16.row.col.f32.bf16.bf16.f32 "
                 "{%0,%1,%2,%3}, {%4,%5,%6,%7}, {%8,%9}, {%0,%1,%2,%3};"
                 : "+f"(c[0]), "+f"(c[1]), "+f"(c[2]), "+f"(c[3])
                 : "r"(a[0]), "r"(a[1]), "r"(a[2]), "r"(a[3]), "r"(b0), "r"(b1));
}
#define CP_COMMIT() asm volatile("cp.async.commit_group;" ::: "memory")
#define CP_WAIT0()  asm volatile("cp.async.wait_group 0;" ::: "memory")

// ---------------- fp32 -> bf16 hi/lo split (elementwise) ----------------
__global__ __launch_bounds__(256) void fsplit_kernel(
    const float* __restrict__ src, __nv_bfloat16* __restrict__ h,
    __nv_bfloat16* __restrict__ l, int n4)
{
    int idx = blockIdx.x * 256 + threadIdx.x;
    if (idx >= n4) return;
    float4 v = ((const float4*)src)[idx];
    __nv_bfloat16 h0 = __float2bfloat16(v.x), h1 = __float2bfloat16(v.y);
    __nv_bfloat16 h2 = __float2bfloat16(v.z), h3 = __float2bfloat16(v.w);
    __nv_bfloat16 l0 = __float2bfloat16(v.x - __bfloat162float(h0));
    __nv_bfloat16 l1 = __float2bfloat16(v.y - __bfloat162float(h1));
    __nv_bfloat16 l2 = __float2bfloat16(v.z - __bfloat162float(h2));
    __nv_bfloat16 l3 = __float2bfloat16(v.w - __bfloat162float(h3));
    ((__nv_bfloat162*)h)[idx * 2 + 0] = __nv_bfloat162(h0, h1);
    ((__nv_bfloat162*)h)[idx * 2 + 1] = __nv_bfloat162(h2, h3);
    ((__nv_bfloat162*)l)[idx * 2 + 0] = __nv_bfloat162(l0, l1);
    ((__nv_bfloat162*)l)[idx * 2 + 1] = __nv_bfloat162(l2, l3);
}

// ---------------- W[K][N] fp32 -> W^T[N][K] bf16 hi/lo ----------------
__global__ __launch_bounds__(256) void wsplit_kernel(
    const float* __restrict__ W0, const float* __restrict__ W1,
    const float* __restrict__ W2, const float* __restrict__ W3,
    __nv_bfloat16* __restrict__ oh, __nv_bfloat16* __restrict__ ol)
{
    __shared__ float t[32][33];
    int z = blockIdx.z;
    const float* W = (z == 0) ? W0 : (z == 1) ? W1 : (z == 2) ? W2 : W3;
    size_t zoff = (size_t)z * DM * DM;
    int bn = blockIdx.x * 32;
    int bk = blockIdx.y * 32;
    int tx = threadIdx.x & 31;
    int ty = threadIdx.x >> 5;
#pragma unroll
    for (int r = 0; r < 4; r++)
        t[ty + 8 * r][tx] = W[(size_t)(bk + ty + 8 * r) * DM + bn + tx];
    __syncthreads();
#pragma unroll
    for (int r = 0; r < 4; r++) {
        int nl = ty + 8 * r;
        float v = t[tx][nl];
        __nv_bfloat16 h = __float2bfloat16(v);
        __nv_bfloat16 l = __float2bfloat16(v - __bfloat162float(h));
        oh[zoff + (size_t)(bn + nl) * DM + bk + tx] = h;
        ol[zoff + (size_t)(bn + nl) * DM + bk + tx] = l;
    }
}

// ---------------- HMMA bf16-split GEMM ----------------
// C[4096,1024] = A[M,K] @ B^T (B stored [N,K] K-major).
// Block 128x128, BK=64, 8 warps (warp tile 32x64), SW128 smem, cp.async
// double buffering. 3 split terms: AhBh + AhBl + AlBh.
#define KC 64
#define TILE_B   (128 * 128)        /* 16KB: 128 rows x 64 bf16 (128B rows) */
#define STAGE_B  (4 * TILE_B)       /* Ah, Al, Bh, Bl */
#define GEMM_SMEM (2 * STAGE_B)     /* 128KB */

__device__ __forceinline__ void load_tile_cp(uint32_t sdst, const __nv_bfloat16* g, int tid) {
#pragma unroll
    for (int i = 0; i < 4; i++) {
        int f = i * 256 + tid;
        int r = f >> 3;
        int q = f & 7;
        uint32_t byte = (uint32_t)(r * 128 + q * 16);
        byte ^= ((byte >> 3) & 0x70);
        const void* src = g + (size_t)r * DM + q * 8;
        asm volatile("cp.async.cg.shared.global [%0], [%1], 16;"
                     :: "r"(sdst + byte), "l"(src) : "memory");
    }
}

__global__ __launch_bounds__(256, 1) void gemm_hmma_kernel(
    const __nv_bfloat16* __restrict__ Ah, const __nv_bfloat16* __restrict__ Al,
    const __nv_bfloat16* __restrict__ Bh_base, const __nv_bfloat16* __restrict__ Bl_base,
    float* __restrict__ C0, float* __restrict__ C1, float* __restrict__ C2,
    const float* __restrict__ bias)
{
    extern __shared__ __align__(1024) char sm[];
    const int tid = threadIdx.x;
    const int wid = tid >> 5;
    const int lane = tid & 31;
    const int z = blockIdx.z;
    const int colBase = blockIdx.x * 128;
    const int rowBase = blockIdx.y * 128;
    const int wm = (wid & 3) * 32;   // warp M offset in tile
    const int wn = (wid >> 2) * 64;  // warp N offset in tile

    const __nv_bfloat16* Bh = Bh_base + (size_t)z * DM * DM;
    const __nv_bfloat16* Bl = Bl_base + (size_t)z * DM * DM;
    float* C = (z == 0) ? C0 : (z == 1) ? C1 : C2;

    const uint32_t sbase = smem_u32(sm);
    const __nv_bfloat16* agh = Ah + (size_t)rowBase * DM;
    const __nv_bfloat16* agl = Al + (size_t)rowBase * DM;
    const __nv_bfloat16* bgh = Bh + (size_t)colBase * DM;
    const __nv_bfloat16* bgl = Bl + (size_t)colBase * DM;

    float acc[2][8][4];
#pragma unroll
    for (int mi = 0; mi < 2; mi++)
#pragma unroll
        for (int nj = 0; nj < 8; nj++)
#pragma unroll
            for (int r = 0; r < 4; r++) acc[mi][nj][r] = 0.f;

    // prologue: stage 0
    {
        uint32_t st = sbase;
        load_tile_cp(st + 0 * TILE_B, agh, tid);
        load_tile_cp(st + 1 * TILE_B, agl, tid);
        load_tile_cp(st + 2 * TILE_B, bgh, tid);
        load_tile_cp(st + 3 * TILE_B, bgl, tid);
        CP_COMMIT();
    }

    const int NCHUNK = DM / KC;  // 16
    // precompute swizzled fragment byte offsets (row-dependent part)
    const int lrow = lane & 15;
    const int lquad = (lane >> 4) << 4;

    for (int c = 0; c < NCHUNK; c++) {
        CP_WAIT0();
        __syncthreads();
        const uint32_t cur = sbase + (uint32_t)(c & 1) * STAGE_B;

        if (c + 1 < NCHUNK) {
            const uint32_t nst = sbase + (uint32_t)((c + 1) & 1) * STAGE_B;
            const int k0 = (c + 1) * KC;
            load_tile_cp(nst + 0 * TILE_B, agh + k0, tid);
            load_tile_cp(nst + 1 * TILE_B, agl + k0, tid);
            load_tile_cp(nst + 2 * TILE_B, bgh + k0, tid);
            load_tile_cp(nst + 3 * TILE_B, bgl + k0, tid);
            CP_COMMIT();
        }

#pragma unroll
        for (int ks = 0; ks < 4; ks++) {
            const uint32_t qoff = ks * 32 + lquad;
            uint32_t sa[2], sb[4];
#pragma unroll
            for (int mi = 0; mi < 2; mi++) {
                uint32_t b = (uint32_t)((wm + mi * 16 + lrow) * 128) + qoff;
                sa[mi] = b ^ ((b >> 3) & 0x70);
            }
#pragma unroll
            for (int ni = 0; ni < 4; ni++) {
                uint32_t b = (uint32_t)((wn + ni * 16 + lrow) * 128) + qoff;
                sb[ni] = b ^ ((b >> 3) & 0x70);
            }
            uint32_t ah[2][4], al[2][4], bh[4][4], bl[4][4];
#pragma unroll
            for (int mi = 0; mi < 2; mi++) {
                ldsm4(ah[mi], cur + 0 * TILE_B + sa[mi]);
                ldsm4(al[mi], cur + 1 * TILE_B + sa[mi]);
            }
#pragma unroll
            for (int ni = 0; ni < 4; ni++) {
                ldsm4(bh[ni], cur + 2 * TILE_B + sb[ni]);
                ldsm4(bl[ni], cur + 3 * TILE_B + sb[ni]);
            }
#pragma unroll
            for (int mi = 0; mi < 2; mi++)
#pragma unroll
                for (int nj = 0; nj < 8; nj++) {
                    const int ni = nj >> 1, s = nj & 1;
                    mma16816(acc[mi][nj], ah[mi], bh[ni][s], bh[ni][s + 2]);
                    mma16816(acc[mi][nj], ah[mi], bl[ni][s], bl[ni][s + 2]);
                    mma16816(acc[mi][nj], al[mi], bh[ni][s], bh[ni][s + 2]);
                }
        }
        __syncthreads();
    }

    // ---- epilogue ----
#pragma unroll
    for (int mi = 0; mi < 2; mi++) {
        const int r0 = rowBase + wm + mi * 16 + (lane >> 2);
#pragma unroll
        for (int nj = 0; nj < 8; nj++) {
            const int col = colBase + wn + nj * 8 + (lane & 3) * 2;
            float2 v0 = make_float2(acc[mi][nj][0], acc[mi][nj][1]);
            float2 v1 = make_float2(acc[mi][nj][2], acc[mi][nj][3]);
            if (bias) {
                float2 bb = *(const float2*)(bias + col);
                v0.x += bb.x; v0.y += bb.y;
                v1.x += bb.x; v1.y += bb.y;
            }
            *(float2*)(C + (size_t)r0 * DM + col) = v0;
            *(float2*)(C + (size_t)(r0 + 8) * DM + col) = v1;
        }
    }
}

// ---------------------------------------------------------------------------
// Register-tiled causal flash attention, fp32 (unchanged from round 2).
// ---------------------------------------------------------------------------
__global__ __launch_bounds__(256) void attn_kernel(
    const float* __restrict__ Q, const float* __restrict__ K,
    const float* __restrict__ V, float* __restrict__ O)
{
    extern __shared__ __align__(16) float smf[];
    float* Qs = smf;             // 64*132
    float* Kt = smf + 8448;      // 64*68
    float* Vs = smf + 12800;     // 64*68
    float* Ps = smf + 17152;     // 64*132

    const int mblk = (int)gridDim.x - 1 - (int)blockIdx.x;
    const int bh = blockIdx.y;
    const int b = bh >> 4;
    const int h = bh & 15;
    const int tid = threadIdx.x;
    const int tx = tid & 15;
    const int ty = tid >> 4;
    const float scale = 0.125f * 1.44269504088896340736f;

    const float* qbase = Q + ((size_t)(b * Sq + mblk * BR)) * DM + h * HDv;
    for (int idx = tid; idx < BR * 16; idx += 256) {
        int row = idx >> 4;
        int d4 = (idx & 15) * 4;
        float4 v = *(const float4*)(qbase + (size_t)row * DM + d4);
        Qs[(d4 + 0) * 132 + row] = v.x * scale;
        Qs[(d4 + 1) * 132 + row] = v.y * scale;
        Qs[(d4 + 2) * 132 + row] = v.z * scale;
        Qs[(d4 + 3) * 132 + row] = v.w * scale;
    }

    float Oa[8][4];
#pragma unroll
    for (int i = 0; i < 8; i++)
#pragma unroll
        for (int j = 0; j < 4; j++) Oa[i][j] = 0.f;
    float mrow[8], lrow[8];
#pragma unroll
    for (int i = 0; i < 8; i++) { mrow[i] = -INFINITY; lrow[i] = 0.f; }

    const int ntiles = 2 * mblk + 2;

    for (int t = 0; t < ntiles; t++) {
        __syncthreads();

        const float* kbase = K + ((size_t)(b * Sq + t * BC)) * DM + h * HDv;
        const float* vbase = V + ((size_t)(b * Sq + t * BC)) * DM + h * HDv;
        for (int idx = tid; idx < BC * 16; idx += 256) {
            int key = idx >> 4;
            int d4 = (idx & 15) * 4;
            float4 kv = *(const float4*)(kbase + (size_t)key * DM + d4);
            Kt[(d4 + 0) * 68 + key] = kv.x;
            Kt[(d4 + 1) * 68 + key] = kv.y;
            Kt[(d4 + 2) * 68 + key] = kv.z;
            Kt[(d4 + 3) * 68 + key] = kv.w;
            float4 vv = *(const float4*)(vbase + (size_t)key * DM + d4);
            *(float4*)&Vs[key * 68 + d4] = vv;
        }
        __syncthreads();

        float S[8][4];
#pragma unroll
        for (int i = 0; i < 8; i++)
#pragma unroll
            for (int j = 0; j < 4; j++) S[i][j] = 0.f;

#pragma unroll 4
        for (int k = 0; k < 64; k++) {
            float4 a0 = *(const float4*)&Qs[k * 132 + ty * 8];
            float4 a1 = *(const float4*)&Qs[k * 132 + ty * 8 + 4];
            float4 bb = *(const float4*)&Kt[k * 68 + tx * 4];
            float a[8] = {a0.x, a0.y, a0.z, a0.w, a1.x, a1.y, a1.z, a1.w};
            float bj[4] = {bb.x, bb.y, bb.z, bb.w};
#pragma unroll
            for (int i = 0; i < 8; i++)
#pragma unroll
                for (int j = 0; j < 4; j++)
                    S[i][j] += a[i] * bj[j];
        }

        if (t >= ntiles - 2) {
            const int rowg = mblk * BR + ty * 8;
            const int colg = t * BC + tx * 4;
#pragma unroll
            for (int i = 0; i < 8; i++)
#pragma unroll
                for (int j = 0; j < 4; j++)
                    if (colg + j > rowg + i) S[i][j] = -1e30f;
        }

#pragma unroll
        for (int i = 0; i < 8; i++) {
            float mt = fmaxf(fmaxf(S[i][0], S[i][1]), fmaxf(S[i][2], S[i][3]));
            mt = fmaxf(mt, __shfl_xor_sync(0xffffffffu, mt, 1));
            mt = fmaxf(mt, __shfl_xor_sync(0xffffffffu, mt, 2));
            mt = fmaxf(mt, __shfl_xor_sync(0xffffffffu, mt, 4));
            mt = fmaxf(mt, __shfl_xor_sync(0xffffffffu, mt, 8));
            float mnew = fmaxf(mrow[i], mt);
            float alpha = exp2f(mrow[i] - mnew);
            mrow[i] = mnew;
            lrow[i] *= alpha;
#pragma unroll
            for (int j = 0; j < 4; j++) Oa[i][j] *= alpha;
            float p0 = exp2f(S[i][0] - mnew);
            float p1 = exp2f(S[i][1] - mnew);
            float p2 = exp2f(S[i][2] - mnew);
            float p3 = exp2f(S[i][3] - mnew);
            S[i][0] = p0; S[i][1] = p1; S[i][2] = p2; S[i][3] = p3;
            float rs = (p0 + p1) + (p2 + p3);
            rs += __shfl_xor_sync(0xffffffffu, rs, 1);
            rs += __shfl_xor_sync(0xffffffffu, rs, 2);
            rs += __shfl_xor_sync(0xffffffffu, rs, 4);
            rs += __shfl_xor_sync(0xffffffffu, rs, 8);
            lrow[i] += rs;
        }

#pragma unroll
        for (int j = 0; j < 4; j++) {
            int col = tx * 4 + j;
            *(float4*)&Ps[col * 132 + ty * 8] =
                make_float4(S[0][j], S[1][j], S[2][j], S[3][j]);
            *(float4*)&Ps[col * 132 + ty * 8 + 4] =
                make_float4(S[4][j], S[5][j], S[6][j], S[7][j]);
        }
        __syncthreads();

#pragma unroll 4
        for (int k = 0; k < 64; k++) {
            float4 a0 = *(const float4*)&Ps[k * 132 + ty * 8];
            float4 a1 = *(const float4*)&Ps[k * 132 + ty * 8 + 4];
            float4 bb = *(const float4*)&Vs[k * 68 + tx * 4];
            float a[8] = {a0.x, a0.y, a0.z, a0.w, a1.x, a1.y, a1.z, a1.w};
            float bj[4] = {bb.x, bb.y, bb.z, bb.w};
#pragma unroll
            for (int i = 0; i < 8; i++)
#pragma unroll
                for (int j = 0; j < 4; j++)
                    Oa[i][j] += a[i] * bj[j];
        }
    }

    float* obase = O + ((size_t)(b * Sq + mblk * BR)) * DM + h * HDv;
#pragma unroll
    for (int i = 0; i < 8; i++) {
        float inv = 1.f / lrow[i];
        float4 v = make_float4(Oa[i][0] * inv, Oa[i][1] * inv,
                               Oa[i][2] * inv, Oa[i][3] * inv);
        *(float4*)(obase + (size_t)(ty * 8 + i) * DM + tx * 4) = v;
    }
}

// ---------------------------------------------------------------------------
extern "C" void kernel_launch(void* const* d_in, const int* in_sizes, int n_in,
                              void* d_out, int out_size)
{
    const float* x  = (const float*)d_in[0];
    const float* Wq = (const float*)d_in[1];
    const float* Wk = (const float*)d_in[2];
    const float* Wv = (const float*)d_in[3];
    const float* Wo = (const float*)d_in[4];
    const float* bo = (const float*)d_in[5];
    float* out = (float*)d_out;

    float *Qp, *Kp, *Vp, *Cp;
    __nv_bfloat16 *xh, *xl, *ch, *cl, *wth, *wtl;
    cudaGetSymbolAddress((void**)&Qp, g_Q);
    cudaGetSymbolAddress((void**)&Kp, g_K);
    cudaGetSymbolAddress((void**)&Vp, g_V);
    cudaGetSymbolAddress((void**)&Cp, g_C);
    cudaGetSymbolAddress((void**)&xh, g_xh);
    cudaGetSymbolAddress((void**)&xl, g_xl);
    cudaGetSymbolAddress((void**)&ch, g_ch);
    cudaGetSymbolAddress((void**)&cl, g_cl);
    cudaGetSymbolAddress((void**)&wth, g_wth);
    cudaGetSymbolAddress((void**)&wtl, g_wtl);

    static int attr_set = 0;
    if (!attr_set) {
        cudaFuncSetAttribute(attn_kernel,
                             cudaFuncAttributeMaxDynamicSharedMemorySize, 25600 * 4);
        cudaFuncSetAttribute(gemm_hmma_kernel,
                             cudaFuncAttributeMaxDynamicSharedMemorySize, GEMM_SMEM);
        attr_set = 1;
    }

    const int n4 = Mrows * DM / 4;
    fsplit_kernel<<<(n4 + 255) / 256, 256>>>(x, xh, xl, n4);
    wsplit_kernel<<<dim3(32, 32, 4), 256>>>(Wq, Wk, Wv, Wo, wth, wtl);

    // QKV projections (fused grid.z = 3)
    gemm_hmma_kernel<<<dim3(DM / 128, Mrows / 128, 3), 256, GEMM_SMEM>>>(
        xh, xl, wth, wtl, Qp, Kp, Vp, nullptr);

    attn_kernel<<<dim3(Sq / BR, Bsz * Hh), 256, 25600 * 4>>>(Qp, Kp, Vp, Cp);

    fsplit_kernel<<<(n4 + 255) / 256, 256>>>(Cp, ch, cl, n4);

    // output projection (+bias)
    gemm_hmma_kernel<<<dim3(DM / 128, Mrows / 128, 1), 256, GEMM_SMEM>>>(
        ch, cl, wth + (size_t)3 * DM * DM, wtl + (size_t)3 * DM * DM,
        out, nullptr, nullptr, bo);
}

// round 5
// speedup vs baseline: 3.2599x; 1.7564x over previous
#include <cuda_runtime.h>
#include <cuda_bf16.h>
#include <math.h>
#include <stdint.h>

#define Bsz 2
#define Sq 2048
#define DM 1024
#define Hh 16
#define HDv 64
#define Mrows (Bsz*Sq)   /* 4096 */

#define QSCALE 0.18033688011112042f   /* 0.125 * log2(e) */

// ---------------- scratch (device globals; no allocs allowed) ----------------
__device__ __nv_bfloat16 g_xh[Mrows*DM];
__device__ __nv_bfloat16 g_xl[Mrows*DM];
__device__ __nv_bfloat16 g_qh[Mrows*DM];
__device__ __nv_bfloat16 g_ql[Mrows*DM];
__device__ __nv_bfloat16 g_kh[Mrows*DM];
__device__ __nv_bfloat16 g_kl[Mrows*DM];
__device__ __nv_bfloat16 g_vh[Mrows*DM];
__device__ __nv_bfloat16 g_vl[Mrows*DM];
__device__ __nv_bfloat16 g_ch[Mrows*DM];
__device__ __nv_bfloat16 g_cl[Mrows*DM];
__device__ __nv_bfloat16 g_wth[4*DM*DM];   // W^T split-hi, [N][K], order q,k,v,o
__device__ __nv_bfloat16 g_wtl[4*DM*DM];   // W^T split-lo

// ---------------- helpers ----------------
__device__ __forceinline__ uint32_t smem_u32(const void* p) {
    uint32_t a;
    asm("{ .reg .u64 t; cvta.to.shared.u64 t, %1; cvt.u32.u64 %0, t; }" : "=r"(a) : "l"(p));
    return a;
}
__device__ __forceinline__ void ldsm4(uint32_t* r, uint32_t addr) {
    asm volatile("ldmatrix.sync.aligned.m8n8.x4.shared.b16 {%0,%1,%2,%3}, [%4];"
                 : "=r"(r[0]), "=r"(r[1]), "=r"(r[2]), "=r"(r[3]) : "r"(addr));
}
__device__ __forceinline__ void ldsm4t(uint32_t* r, uint32_t addr) {
    asm volatile("ldmatrix.sync.aligned.m8n8.x4.trans.shared.b16 {%0,%1,%2,%3}, [%4];"
                 : "=r"(r[0]), "=r"(r[1]), "=r"(r[2]), "=r"(r[3]) : "r"(addr));
}
__device__ __forceinline__ void mma16816(float* c, const uint32_t* a, uint32_t b0, uint32_t b1) {
    asm volatile("mma.sync.aligned.m16n8k16.row.col.f32.bf16.bf16.f32 "
                 "{%0,%1,%2,%3}, {%4,%5,%6,%7}, {%8,%9}, {%0,%1,%2,%3};"
                 : "+f"(c[0]), "+f"(c[1]), "+f"(c[2]), "+f"(c[3])
                 : "r"(a[0]), "r"(a[1]), "r"(a[2]), "r"(a[3]), "r"(b0), "r"(b1));
}
#define CP_COMMIT() asm volatile("cp.async.commit_group;" ::: "memory")
#define CP_WAIT0()  asm volatile("cp.async.wait_group 0;" ::: "memory")
#define CP16(dst, src) asm volatile("cp.async.cg.shared.global [%0], [%1], 16;" :: "r"(dst), "l"(src) : "memory")

__device__ __forceinline__ uint32_t packbf2(float x, float y) {
    __nv_bfloat162 t = __floats2bfloat162_rn(x, y);
    return *(uint32_t*)&t;
}
// split a pair of floats into bf16 hi + bf16 lo packed regs
__device__ __forceinline__ void split2(float x, float y, uint32_t& h, uint32_t& l) {
    __nv_bfloat16 hx = __float2bfloat16(x), hy = __float2bfloat16(y);
    __nv_bfloat162 hh; hh.x = hx; hh.y = hy;
    h = *(uint32_t*)&hh;
    l = packbf2(x - __bfloat162float(hx), y - __bfloat162float(hy));
}
// fast exp2 for x <= 0: magic round + degree-5 Taylor (err ~3e-6); FFMA pipe only
__device__ __forceinline__ float exp2p(float x) {
    x = fmaxf(x, -60.0f);
    float r = x + 12582912.0f;              // round to nearest int
    int n = __float_as_int(r) - 0x4B400000;
    float f = x - (r - 12582912.0f);        // f in [-0.5, 0.5]
    float p = 1.3333558e-3f;
    p = fmaf(p, f, 9.6181291e-3f);
    p = fmaf(p, f, 5.5504109e-2f);
    p = fmaf(p, f, 2.4022651e-1f);
    p = fmaf(p, f, 6.9314718e-1f);
    p = fmaf(p, f, 1.0f);
    return __int_as_float(__float_as_int(p) + (n << 23));
}

// ---------------- fp32 -> bf16 hi/lo split (elementwise) ----------------
__global__ __launch_bounds__(256) void fsplit_kernel(
    const float* __restrict__ src, __nv_bfloat16* __restrict__ h,
    __nv_bfloat16* __restrict__ l, int n4)
{
    int idx = blockIdx.x * 256 + threadIdx.x;
    if (idx >= n4) return;
    float4 v = ((const float4*)src)[idx];
    uint32_t h0, l0, h1, l1;
    split2(v.x, v.y, h0, l0);
    split2(v.z, v.w, h1, l1);
    ((uint32_t*)h)[idx * 2 + 0] = h0;
    ((uint32_t*)h)[idx * 2 + 1] = h1;
    ((uint32_t*)l)[idx * 2 + 0] = l0;
    ((uint32_t*)l)[idx * 2 + 1] = l1;
}

// ---------------- W[K][N] fp32 -> W^T[N][K] bf16 hi/lo ----------------
__global__ __launch_bounds__(256) void wsplit_kernel(
    const float* __restrict__ W0, const float* __restrict__ W1,
    const float* __restrict__ W2, const float* __restrict__ W3,
    __nv_bfloat16* __restrict__ oh, __nv_bfloat16* __restrict__ ol)
{
    __shared__ float t[32][33];
    int z = blockIdx.z;
    const float* W = (z == 0) ? W0 : (z == 1) ? W1 : (z == 2) ? W2 : W3;
    size_t zoff = (size_t)z * DM * DM;
    int bn = blockIdx.x * 32;
    int bk = blockIdx.y * 32;
    int tx = threadIdx.x & 31;
    int ty = threadIdx.x >> 5;
#pragma unroll
    for (int r = 0; r < 4; r++)
        t[ty + 8 * r][tx] = W[(size_t)(bk + ty + 8 * r) * DM + bn + tx];
    __syncthreads();
#pragma unroll
    for (int r = 0; r < 4; r++) {
        int nl = ty + 8 * r;
        float v = t[tx][nl];
        __nv_bfloat16 h = __float2bfloat16(v);
        __nv_bfloat16 l = __float2bfloat16(v - __bfloat162float(h));
        oh[zoff + (size_t)(bn + nl) * DM + bk + tx] = h;
        ol[zoff + (size_t)(bn + nl) * DM + bk + tx] = l;
    }
}

// ---------------- HMMA bf16-split GEMM ----------------
// C[4096,1024] = A[M,K] @ B^T (B stored [N,K] K-major).
// Block 128x128, BK=64, 8 warps (warp tile 32x64), SW128 smem, cp.async
// double buffering. 3 split terms: AhBh + AhBl + AlBh.
// SPLIT epilogue emits bf16 hi/lo pairs (optionally scaled); else fp32 (+bias).
#define KC 64
#define TILE_B   (128 * 128)
#define STAGE_B  (4 * TILE_B)
#define GEMM_SMEM (2 * STAGE_B)

__device__ __forceinline__ void load_tile_cp(uint32_t sdst, const __nv_bfloat16* g, int tid) {
#pragma unroll
    for (int i = 0; i < 4; i++) {
        int f = i * 256 + tid;
        int r = f >> 3;
        int q = f & 7;
        uint32_t byte = (uint32_t)(r * 128 + q * 16);
        byte ^= ((byte >> 3) & 0x70);
        CP16(sdst + byte, g + (size_t)r * DM + q * 8);
    }
}

template<bool SPLIT>
__global__ __launch_bounds__(256, 1) void gemm_hmma_kernel(
    const __nv_bfloat16* __restrict__ Ah, const __nv_bfloat16* __restrict__ Al,
    const __nv_bfloat16* __restrict__ Bh_base, const __nv_bfloat16* __restrict__ Bl_base,
    __nv_bfloat16* H0, __nv_bfloat16* L0,
    __nv_bfloat16* H1, __nv_bfloat16* L1,
    __nv_bfloat16* H2, __nv_bfloat16* L2,
    float* __restrict__ Cf, const float* __restrict__ bias)
{
    extern __shared__ __align__(1024) char sm[];
    const int tid = threadIdx.x;
    const int wid = tid >> 5;
    const int lane = tid & 31;
    const int z = blockIdx.z;
    const int colBase = blockIdx.x * 128;
    const int rowBase = blockIdx.y * 128;
    const int wm = (wid & 3) * 32;
    const int wn = (wid >> 2) * 64;

    const __nv_bfloat16* Bh = Bh_base + (size_t)z * DM * DM;
    const __nv_bfloat16* Bl = Bl_base + (size_t)z * DM * DM;

    const uint32_t sbase = smem_u32(sm);
    const __nv_bfloat16* agh = Ah + (size_t)rowBase * DM;
    const __nv_bfloat16* agl = Al + (size_t)rowBase * DM;
    const __nv_bfloat16* bgh = Bh + (size_t)colBase * DM;
    const __nv_bfloat16* bgl = Bl + (size_t)colBase * DM;

    float acc[2][8][4];
#pragma unroll
    for (int mi = 0; mi < 2; mi++)
#pragma unroll
        for (int nj = 0; nj < 8; nj++)
#pragma unroll
            for (int r = 0; r < 4; r++) acc[mi][nj][r] = 0.f;

    {
        load_tile_cp(sbase + 0 * TILE_B, agh, tid);
        load_tile_cp(sbase + 1 * TILE_B, agl, tid);
        load_tile_cp(sbase + 2 * TILE_B, bgh, tid);
        load_tile_cp(sbase + 3 * TILE_B, bgl, tid);
        CP_COMMIT();
    }

    const int NCHUNK = DM / KC;
    const int lrow = lane & 15;
    const int lquad = (lane >> 4) << 4;

    for (int c = 0; c < NCHUNK; c++) {
        CP_WAIT0();
        __syncthreads();
        const uint32_t cur = sbase + (uint32_t)(c & 1) * STAGE_B;

        if (c + 1 < NCHUNK) {
            const uint32_t nst = sbase + (uint32_t)((c + 1) & 1) * STAGE_B;
            const int k0 = (c + 1) * KC;
            load_tile_cp(nst + 0 * TILE_B, agh + k0, tid);
            load_tile_cp(nst + 1 * TILE_B, agl + k0, tid);
            load_tile_cp(nst + 2 * TILE_B, bgh + k0, tid);
            load_tile_cp(nst + 3 * TILE_B, bgl + k0, tid);
            CP_COMMIT();
        }

#pragma unroll
        for (int ks = 0; ks < 4; ks++) {
            const uint32_t qoff = ks * 32 + lquad;
            uint32_t sa[2], sb[4];
#pragma unroll
            for (int mi = 0; mi < 2; mi++) {
                uint32_t b = (uint32_t)((wm + mi * 16 + lrow) * 128) + qoff;
                sa[mi] = b ^ ((b >> 3) & 0x70);
            }
#pragma unroll
            for (int ni = 0; ni < 4; ni++) {
                uint32_t b = (uint32_t)((wn + ni * 16 + lrow) * 128) + qoff;
                sb[ni] = b ^ ((b >> 3) & 0x70);
            }
            uint32_t ah[2][4], al[2][4], bh[4][4], bl[4][4];
#pragma unroll
            for (int mi = 0; mi < 2; mi++) {
                ldsm4(ah[mi], cur + 0 * TILE_B + sa[mi]);
                ldsm4(al[mi], cur + 1 * TILE_B + sa[mi]);
            }
#pragma unroll
            for (int ni = 0; ni < 4; ni++) {
                ldsm4(bh[ni], cur + 2 * TILE_B + sb[ni]);
                ldsm4(bl[ni], cur + 3 * TILE_B + sb[ni]);
            }
#pragma unroll
            for (int mi = 0; mi < 2; mi++)
#pragma unroll
                for (int nj = 0; nj < 8; nj++) {
                    const int ni = nj >> 1, s = nj & 1;
                    mma16816(acc[mi][nj], ah[mi], bh[ni][s], bh[ni][s + 2]);
                    mma16816(acc[mi][nj], ah[mi], bl[ni][s], bl[ni][s + 2]);
                    mma16816(acc[mi][nj], al[mi], bh[ni][s], bh[ni][s + 2]);
                }
        }
        __syncthreads();
    }

    // ---- epilogue ----
    if (SPLIT) {
        __nv_bfloat16* H = (z == 0) ? H0 : (z == 1) ? H1 : H2;
        __nv_bfloat16* L = (z == 0) ? L0 : (z == 1) ? L1 : L2;
        const float sc = (z == 0) ? QSCALE : 1.0f;
#pragma unroll
        for (int mi = 0; mi < 2; mi++) {
            const int r0 = rowBase + wm + mi * 16 + (lane >> 2);
#pragma unroll
            for (int nj = 0; nj < 8; nj++) {
                const int col = colBase + wn + nj * 8 + (lane & 3) * 2;
                uint32_t h0, l0, h1, l1;
                split2(acc[mi][nj][0] * sc, acc[mi][nj][1] * sc, h0, l0);
                split2(acc[mi][nj][2] * sc, acc[mi][nj][3] * sc, h1, l1);
                *(uint32_t*)(H + (size_t)r0 * DM + col) = h0;
                *(uint32_t*)(L + (size_t)r0 * DM + col) = l0;
                *(uint32_t*)(H + (size_t)(r0 + 8) * DM + col) = h1;
                *(uint32_t*)(L + (size_t)(r0 + 8) * DM + col) = l1;
            }
        }
    } else {
#pragma unroll
        for (int mi = 0; mi < 2; mi++) {
            const int r0 = rowBase + wm + mi * 16 + (lane >> 2);
#pragma unroll
            for (int nj = 0; nj < 8; nj++) {
                const int col = colBase + wn + nj * 8 + (lane & 3) * 2;
                float2 bb = *(const float2*)(bias + col);
                float2 v0 = make_float2(acc[mi][nj][0] + bb.x, acc[mi][nj][1] + bb.y);
                float2 v1 = make_float2(acc[mi][nj][2] + bb.x, acc[mi][nj][3] + bb.y);
                *(float2*)(Cf + (size_t)r0 * DM + col) = v0;
                *(float2*)(Cf + (size_t)(r0 + 8) * DM + col) = v1;
            }
        }
    }
}

// ---------------- HMMA causal flash attention ----------------
// Block: 256 thr (8 warps), 128 queries x 64-key tiles, one (b,h) per block.y.
// Warp w owns q-rows w*16..w*16+15. Q frags persist in regs.
// S = QhKh + QhKl + QlKh (fp32 acc); softmax via FFMA exp2 poly;
// P split to bf16 hi/lo in-register; O += PhVh + PhVl + PlVh (V^T via ldmatrix.trans).
// SMEM: 2 stages x (Kh|Kl|Vh|Vl, each 64x64 bf16 SW128) = 64KB.
#define AT_STAGE 32768
#define AT_SMEM  (2 * AT_STAGE)

__device__ __forceinline__ void load_kv_tiles(
    uint32_t sdst, const __nv_bfloat16* kh, const __nv_bfloat16* kl,
    const __nv_bfloat16* vh, const __nv_bfloat16* vl, int tid)
{
#pragma unroll
    for (int i = 0; i < 2; i++) {
        int f = i * 256 + tid;          // 0..511
        int r = f >> 3;                 // key row 0..63
        int q = f & 7;
        uint32_t byte = (uint32_t)(r * 128 + q * 16);
        byte ^= ((byte >> 3) & 0x70);
        size_t go = (size_t)r * DM + q * 8;
        CP16(sdst + byte,         kh + go);
        CP16(sdst + 8192 + byte,  kl + go);
        CP16(sdst + 16384 + byte, vh + go);
        CP16(sdst + 24576 + byte, vl + go);
    }
}

__global__ __launch_bounds__(256, 1) void attn_mma_kernel(
    const __nv_bfloat16* __restrict__ Qh, const __nv_bfloat16* __restrict__ Ql,
    const __nv_bfloat16* __restrict__ Kh, const __nv_bfloat16* __restrict__ Kl,
    const __nv_bfloat16* __restrict__ Vh, const __nv_bfloat16* __restrict__ Vl,
    __nv_bfloat16* __restrict__ Ch, __nv_bfloat16* __restrict__ Cl)
{
    extern __shared__ __align__(1024) char sm[];
    const uint32_t sb = smem_u32(sm);
    const int tid = threadIdx.x;
    const int wid = tid >> 5;
    const int lane = tid & 31;
    const int mblk = (int)gridDim.x - 1 - (int)blockIdx.x;  // heavy-first
    const int bh = blockIdx.y;
    const int b = bh >> 4;
    const int h = bh & 15;
    const size_t headoff = (size_t)(b * Sq) * DM + h * HDv;
    const int wrow = wid * 16;
    const int lrow = lane & 15;
    const int lq = (lane >> 4) * 16;

    // ---- prologue: stage Q tile (128x64 hi+lo) into stage0 area, ldmatrix ----
    const __nv_bfloat16* qgh = Qh + headoff + (size_t)(mblk * 128) * DM;
    const __nv_bfloat16* qgl = Ql + headoff + (size_t)(mblk * 128) * DM;
#pragma unroll
    for (int i = 0; i < 4; i++) {
        int f = i * 256 + tid;
        int r = f >> 3;
        int q = f & 7;
        uint32_t byte = (uint32_t)(r * 128 + q * 16);
        byte ^= ((byte >> 3) & 0x70);
        size_t go = (size_t)r * DM + q * 8;
        CP16(sb + byte, qgh + go);
        CP16(sb + 16384 + byte, qgl + go);
    }
    CP_COMMIT();
    CP_WAIT0();
    __syncthreads();

    uint32_t qfh[4][4], qfl[4][4];
#pragma unroll
    for (int ks = 0; ks < 4; ks++) {
        uint32_t byte = (uint32_t)((wrow + lrow) * 128) + ks * 32 + lq;
        byte ^= ((byte >> 3) & 0x70);
        ldsm4(qfh[ks], sb + byte);
        ldsm4(qfl[ks], sb + 16384 + byte);
    }
    __syncthreads();

    // ---- tile 0 KV loads ----
    const __nv_bfloat16* kgh = Kh + headoff;
    const __nv_bfloat16* kgl = Kl + headoff;
    const __nv_bfloat16* vgh = Vh + headoff;
    const __nv_bfloat16* vgl = Vl + headoff;
    load_kv_tiles(sb, kgh, kgl, vgh, vgl, tid);
    CP_COMMIT();

    float Oacc[8][4];
#pragma unroll
    for (int nj = 0; nj < 8; nj++)
#pragma unroll
        for (int r = 0; r < 4; r++) Oacc[nj][r] = 0.f;
    float m0 = -INFINITY, m1 = -INFINITY, l0 = 0.f, l1 = 0.f;

    const int ntiles = 2 * mblk + 2;

    for (int t = 0; t < ntiles; t++) {
        CP_WAIT0();
        __syncthreads();
        const uint32_t cur = sb + (uint32_t)(t & 1) * AT_STAGE;

        if (t + 1 < ntiles) {
            const size_t off = (size_t)((t + 1) * 64) * DM;
            load_kv_tiles(sb + (uint32_t)((t + 1) & 1) * AT_STAGE,
                          kgh + off, kgl + off, vgh + off, vgl + off, tid);
            CP_COMMIT();
        }

        // ---- S = Q K^T (3 split terms) ----
        float S[8][4];
#pragma unroll
        for (int nj = 0; nj < 8; nj++)
#pragma unroll
            for (int r = 0; r < 4; r++) S[nj][r] = 0.f;

#pragma unroll
        for (int ks = 0; ks < 4; ks++) {
            uint32_t kf_h[4][4], kf_l[4][4];
#pragma unroll
            for (int ni = 0; ni < 4; ni++) {
                uint32_t byte = (uint32_t)((ni * 16 + lrow) * 128) + ks * 32 + lq;
                byte ^= ((byte >> 3) & 0x70);
                ldsm4(kf_h[ni], cur + byte);
                ldsm4(kf_l[ni], cur + 8192 + byte);
            }
#pragma unroll
            for (int nj = 0; nj < 8; nj++) {
                const int ni = nj >> 1, s = nj & 1;
                mma16816(S[nj], qfh[ks], kf_h[ni][s], kf_h[ni][s + 2]);
                mma16816(S[nj], qfh[ks], kf_l[ni][s], kf_l[ni][s + 2]);
                mma16816(S[nj], qfl[ks], kf_h[ni][s], kf_h[ni][s + 2]);
            }
        }

        // ---- causal mask (last two tiles only) ----
        if (t >= ntiles - 2) {
            const int rg0 = mblk * 128 + wrow + (lane >> 2);
            const int rg1 = rg0 + 8;
            const int cb = t * 64 + (lane & 3) * 2;
#pragma unroll
            for (int nj = 0; nj < 8; nj++) {
                const int c0 = cb + nj * 8, c1 = c0 + 1;
                if (c0 > rg0) S[nj][0] = -1e30f;
                if (c1 > rg0) S[nj][1] = -1e30f;
                if (c0 > rg1) S[nj][2] = -1e30f;
                if (c1 > rg1) S[nj][3] = -1e30f;
            }
        }

        // ---- online softmax (exp2 poly on FFMA pipe) ----
        float mt0 = -INFINITY, mt1 = -INFINITY;
#pragma unroll
        for (int nj = 0; nj < 8; nj++) {
            mt0 = fmaxf(mt0, fmaxf(S[nj][0], S[nj][1]));
            mt1 = fmaxf(mt1, fmaxf(S[nj][2], S[nj][3]));
        }
        mt0 = fmaxf(mt0, __shfl_xor_sync(0xffffffffu, mt0, 1));
        mt0 = fmaxf(mt0, __shfl_xor_sync(0xffffffffu, mt0, 2));
        mt1 = fmaxf(mt1, __shfl_xor_sync(0xffffffffu, mt1, 1));
        mt1 = fmaxf(mt1, __shfl_xor_sync(0xffffffffu, mt1, 2));
        const float mn0 = fmaxf(m0, mt0), mn1 = fmaxf(m1, mt1);
        const float a0 = exp2p(m0 - mn0), a1 = exp2p(m1 - mn1);
        m0 = mn0; m1 = mn1;
        l0 *= a0; l1 *= a1;
        float rs0 = 0.f, rs1 = 0.f;
#pragma unroll
        for (int nj = 0; nj < 8; nj++) {
            Oacc[nj][0] *= a0; Oacc[nj][1] *= a0;
            Oacc[nj][2] *= a1; Oacc[nj][3] *= a1;
            S[nj][0] = exp2p(S[nj][0] - mn0);
            S[nj][1] = exp2p(S[nj][1] - mn0);
            S[nj][2] = exp2p(S[nj][2] - mn1);
            S[nj][3] = exp2p(S[nj][3] - mn1);
            rs0 += S[nj][0] + S[nj][1];
            rs1 += S[nj][2] + S[nj][3];
        }
        l0 += rs0; l1 += rs1;   // lane-partial; quad-reduced at epilogue

        // ---- O += P V (3 split terms; V^T via ldmatrix.trans) ----
#pragma unroll
        for (int kk = 0; kk < 4; kk++) {
            uint32_t pah[4], pal[4];
            split2(S[2 * kk][0],     S[2 * kk][1],     pah[0], pal[0]);
            split2(S[2 * kk][2],     S[2 * kk][3],     pah[1], pal[1]);
            split2(S[2 * kk + 1][0], S[2 * kk + 1][1], pah[2], pal[2]);
            split2(S[2 * kk + 1][2], S[2 * kk + 1][3], pah[3], pal[3]);
#pragma unroll
            for (int dp = 0; dp < 4; dp++) {
                uint32_t byte = (uint32_t)((kk * 16 + lrow) * 128) + dp * 32 + lq;
                byte ^= ((byte >> 3) & 0x70);
                uint32_t vfh[4], vfl[4];
                ldsm4t(vfh, cur + 16384 + byte);
                ldsm4t(vfl, cur + 24576 + byte);
                mma16816(Oacc[2 * dp], pah, vfh[0], vfh[1]);
                mma16816(Oacc[2 * dp], pah, vfl[0], vfl[1]);
                mma16816(Oacc[2 * dp], pal, vfh[0], vfh[1]);
                mma16816(Oacc[2 * dp + 1], pah, vfh[2], vfh[3]);
                mma16816(Oacc[2 * dp + 1], pah, vfl[2], vfl[3]);
                mma16816(Oacc[2 * dp + 1], pal, vfh[2], vfh[3]);
            }
        }
    }

    // ---- epilogue: reduce l over quad, normalize, split-store ----
    l0 += __shfl_xor_sync(0xffffffffu, l0, 1);
    l0 += __shfl_xor_sync(0xffffffffu, l0, 2);
    l1 += __shfl_xor_sync(0xffffffffu, l1, 1);
    l1 += __shfl_xor_sync(0xffffffffu, l1, 2);
    const float inv0 = 1.f / l0, inv1 = 1.f / l1;
    const size_t tok0 = (size_t)(b * Sq + mblk * 128 + wrow + (lane >> 2));
    const size_t tok1 = tok0 + 8;
    const int colb = h * HDv + (lane & 3) * 2;
#pragma unroll
    for (int nj = 0; nj < 8; nj++) {
        const int col = colb + nj * 8;
        uint32_t h0, lo0, h1, lo1;
        split2(Oacc[nj][0] * inv0, Oacc[nj][1] * inv0, h0, lo0);
        split2(Oacc[nj][2] * inv1, Oacc[nj][3] * inv1, h1, lo1);
        *(uint32_t*)(Ch + tok0 * DM + col) = h0;
        *(uint32_t*)(Cl + tok0 * DM + col) = lo0;
        *(uint32_t*)(Ch + tok1 * DM + col) = h1;
        *(uint32_t*)(Cl + tok1 * DM + col) = lo1;
    }
}

// ---------------------------------------------------------------------------
extern "C" void kernel_launch(void* const* d_in, const int* in_sizes, int n_in,
                              void* d_out, int out_size)
{
    const float* x  = (const float*)d_in[0];
    const float* Wq = (const float*)d_in[1];
    const float* Wk = (const float*)d_in[2];
    const float* Wv = (const float*)d_in[3];
    const float* Wo = (const float*)d_in[4];
    const float* bo = (const float*)d_in[5];
    float* out = (float*)d_out;

    __nv_bfloat16 *xh, *xl, *qh, *ql, *kh, *kl, *vh, *vl, *ch, *cl, *wth, *wtl;
    cudaGetSymbolAddress((void**)&xh, g_xh);
    cudaGetSymbolAddress((void**)&xl, g_xl);
    cudaGetSymbolAddress((void**)&qh, g_qh);
    cudaGetSymbolAddress((void**)&ql, g_ql);
    cudaGetSymbolAddress((void**)&kh, g_kh);
    cudaGetSymbolAddress((void**)&kl, g_kl);
    cudaGetSymbolAddress((void**)&vh, g_vh);
    cudaGetSymbolAddress((void**)&vl, g_vl);
    cudaGetSymbolAddress((void**)&ch, g_ch);
    cudaGetSymbolAddress((void**)&cl, g_cl);
    cudaGetSymbolAddress((void**)&wth, g_wth);
    cudaGetSymbolAddress((void**)&wtl, g_wtl);

    static int attr_set = 0;
    if (!attr_set) {
        cudaFuncSetAttribute(gemm_hmma_kernel<true>,
                             cudaFuncAttributeMaxDynamicSharedMemorySize, GEMM_SMEM);
        cudaFuncSetAttribute(gemm_hmma_kernel<false>,
                             cudaFuncAttributeMaxDynamicSharedMemorySize, GEMM_SMEM);
        cudaFuncSetAttribute(attn_mma_kernel,
                             cudaFuncAttributeMaxDynamicSharedMemorySize, AT_SMEM);
        attr_set = 1;
    }

    const int n4 = Mrows * DM / 4;
    fsplit_kernel<<<(n4 + 255) / 256, 256>>>(x, xh, xl, n4);
    wsplit_kernel<<<dim3(32, 32, 4), 256>>>(Wq, Wk, Wv, Wo, wth, wtl);

    // QKV projections -> split bf16 outputs (Q pre-scaled by 0.125*log2e)
    gemm_hmma_kernel<true><<<dim3(DM / 128, Mrows / 128, 3), 256, GEMM_SMEM>>>(
        xh, xl, wth, wtl, qh, ql, kh, kl, vh, vl, nullptr, nullptr);

    attn_mma_kernel<<<dim3(Sq / 128, Bsz * Hh), 256, AT_SMEM>>>(
        qh, ql, kh, kl, vh, vl, ch, cl);

    // output projection (+bias)
    gemm_hmma_kernel<false><<<dim3(DM / 128, Mrows / 128, 1), 256, GEMM_SMEM>>>(
        ch, cl, wth + (size_t)3 * DM * DM, wtl + (size_t)3 * DM * DM,
        nullptr, nullptr, nullptr, nullptr, nullptr, nullptr, out, bo);
}

// round 6
// speedup vs baseline: 3.3631x; 1.0316x over previous
#include <cuda_runtime.h>
#include <cuda_bf16.h>
#include <math.h>
#include <stdint.h>

#define Bsz 2
#define Sq 2048
#define DM 1024
#define Hh 16
#define HDv 64
#define Mrows (Bsz*Sq)   /* 4096 */

#define QSCALE 0.18033688011112042f   /* 0.125 * log2(e) */

// ---------------- scratch (device globals; no allocs allowed) ----------------
__device__ __nv_bfloat16 g_xh[Mrows*DM];
__device__ __nv_bfloat16 g_xl[Mrows*DM];
__device__ __nv_bfloat16 g_qh[Mrows*DM];
__device__ __nv_bfloat16 g_ql[Mrows*DM];
__device__ __nv_bfloat16 g_kh[Mrows*DM];
__device__ __nv_bfloat16 g_kl[Mrows*DM];
__device__ __nv_bfloat16 g_vh[Mrows*DM];
__device__ __nv_bfloat16 g_vl[Mrows*DM];
__device__ __nv_bfloat16 g_ch[Mrows*DM];
__device__ __nv_bfloat16 g_cl[Mrows*DM];
__device__ __nv_bfloat16 g_wth[4*DM*DM];   // W^T split-hi, [N][K], order q,k,v,o
__device__ __nv_bfloat16 g_wtl[4*DM*DM];   // W^T split-lo

// ---------------- helpers ----------------
__device__ __forceinline__ uint32_t smem_u32(const void* p) {
    uint32_t a;
    asm("{ .reg .u64 t; cvta.to.shared.u64 t, %1; cvt.u32.u64 %0, t; }" : "=r"(a) : "l"(p));
    return a;
}
__device__ __forceinline__ void ldsm4(uint32_t* r, uint32_t addr) {
    asm volatile("ldmatrix.sync.aligned.m8n8.x4.shared.b16 {%0,%1,%2,%3}, [%4];"
                 : "=r"(r[0]), "=r"(r[1]), "=r"(r[2]), "=r"(r[3]) : "r"(addr));
}
__device__ __forceinline__ void ldsm4t(uint32_t* r, uint32_t addr) {
    asm volatile("ldmatrix.sync.aligned.m8n8.x4.trans.shared.b16 {%0,%1,%2,%3}, [%4];"
                 : "=r"(r[0]), "=r"(r[1]), "=r"(r[2]), "=r"(r[3]) : "r"(addr));
}
__device__ __forceinline__ void mma16816(float* c, const uint32_t* a, uint32_t b0, uint32_t b1) {
    asm volatile("mma.sync.aligned.m16n8k16.row.col.f32.bf16.bf16.f32 "
                 "{%0,%1,%2,%3}, {%4,%5,%6,%7}, {%8,%9}, {%0,%1,%2,%3};"
                 : "+f"(c[0]), "+f"(c[1]), "+f"(c[2]), "+f"(c[3])
                 : "r"(a[0]), "r"(a[1]), "r"(a[2]), "r"(a[3]), "r"(b0), "r"(b1));
}
#define CP_COMMIT() asm volatile("cp.async.commit_group;" ::: "memory")
#define CP_WAIT0()  asm volatile("cp.async.wait_group 0;" ::: "memory")
#define CP16(dst, src) asm volatile("cp.async.cg.shared.global [%0], [%1], 16;" :: "r"(dst), "l"(src) : "memory")

__device__ __forceinline__ uint32_t packbf2(float x, float y) {
    __nv_bfloat162 t = __floats2bfloat162_rn(x, y);
    return *(uint32_t*)&t;
}
// split a pair of floats into bf16 hi + bf16 lo packed regs
__device__ __forceinline__ void split2(float x, float y, uint32_t& h, uint32_t& l) {
    __nv_bfloat16 hx = __float2bfloat16(x), hy = __float2bfloat16(y);
    __nv_bfloat162 hh; hh.x = hx; hh.y = hy;
    h = *(uint32_t*)&hh;
    l = packbf2(x - __bfloat162float(hx), y - __bfloat162float(hy));
}
// fast exp2 for x <= 0: magic round + degree-5 Taylor (err ~3e-6); FFMA pipe only
__device__ __forceinline__ float exp2p(float x) {
    x = fmaxf(x, -60.0f);
    float r = x + 12582912.0f;
    int n = __float_as_int(r) - 0x4B400000;
    float f = x - (r - 12582912.0f);
    float p = 1.3333558e-3f;
    p = fmaf(p, f, 9.6181291e-3f);
    p = fmaf(p, f, 5.5504109e-2f);
    p = fmaf(p, f, 2.4022651e-1f);
    p = fmaf(p, f, 6.9314718e-1f);
    p = fmaf(p, f, 1.0f);
    return __int_as_float(__float_as_int(p) + (n << 23));
}

// ---------------- fp32 -> bf16 hi/lo split (elementwise) ----------------
__global__ __launch_bounds__(256) void fsplit_kernel(
    const float* __restrict__ src, __nv_bfloat16* __restrict__ h,
    __nv_bfloat16* __restrict__ l, int n4)
{
    int idx = blockIdx.x * 256 + threadIdx.x;
    if (idx >= n4) return;
    float4 v = ((const float4*)src)[idx];
    uint32_t h0, l0, h1, l1;
    split2(v.x, v.y, h0, l0);
    split2(v.z, v.w, h1, l1);
    ((uint32_t*)h)[idx * 2 + 0] = h0;
    ((uint32_t*)h)[idx * 2 + 1] = h1;
    ((uint32_t*)l)[idx * 2 + 0] = l0;
    ((uint32_t*)l)[idx * 2 + 1] = l1;
}

// ---------------- W[K][N] fp32 -> W^T[N][K] bf16 hi/lo ----------------
__global__ __launch_bounds__(256) void wsplit_kernel(
    const float* __restrict__ W0, const float* __restrict__ W1,
    const float* __restrict__ W2, const float* __restrict__ W3,
    __nv_bfloat16* __restrict__ oh, __nv_bfloat16* __restrict__ ol)
{
    __shared__ float t[32][33];
    int z = blockIdx.z;
    const float* W = (z == 0) ? W0 : (z == 1) ? W1 : (z == 2) ? W2 : W3;
    size_t zoff = (size_t)z * DM * DM;
    int bn = blockIdx.x * 32;
    int bk = blockIdx.y * 32;
    int tx = threadIdx.x & 31;
    int ty = threadIdx.x >> 5;
#pragma unroll
    for (int r = 0; r < 4; r++)
        t[ty + 8 * r][tx] = W[(size_t)(bk + ty + 8 * r) * DM + bn + tx];
    __syncthreads();
#pragma unroll
    for (int r = 0; r < 4; r++) {
        int nl = ty + 8 * r;
        float v = t[tx][nl];
        __nv_bfloat16 h = __float2bfloat16(v);
        __nv_bfloat16 l = __float2bfloat16(v - __bfloat162float(h));
        oh[zoff + (size_t)(bn + nl) * DM + bk + tx] = h;
        ol[zoff + (size_t)(bn + nl) * DM + bk + tx] = l;
    }
}

// ---------------- HMMA bf16-split GEMM ----------------
// C[4096,1024] = A[M,K] @ B^T (B stored [N,K] K-major).
// Block tile 256x128, BK=64, 8 warps, warp tile 64x64 (1:6 ldsm:mma).
// SW128 smem, cp.async double buffering (2 x 96KB stages).
// 3 split terms: AhBh + AhBl + AlBh.
#define A_TILE_B (256 * 128)        /* 32KB */
#define B_TILE_B (128 * 128)        /* 16KB */
#define STAGE_B  (2 * A_TILE_B + 2 * B_TILE_B)   /* 96KB: Ah, Al, Bh, Bl */
#define OFF_AL   A_TILE_B
#define OFF_BH   (2 * A_TILE_B)
#define OFF_BL   (2 * A_TILE_B + B_TILE_B)
#define GEMM_SMEM (2 * STAGE_B)     /* 192KB */

__device__ __forceinline__ void load_tile_cp(uint32_t sdst, const __nv_bfloat16* g,
                                             int tid, int niter) {
#pragma unroll
    for (int i = 0; i < 8; i++) {
        if (i >= niter) break;
        int f = i * 256 + tid;
        int r = f >> 3;
        int q = f & 7;
        uint32_t byte = (uint32_t)(r * 128 + q * 16);
        byte ^= ((byte >> 3) & 0x70);
        CP16(sdst + byte, g + (size_t)r * DM + q * 8);
    }
}

template<bool SPLIT>
__global__ __launch_bounds__(256, 1) void gemm_hmma_kernel(
    const __nv_bfloat16* __restrict__ Ah, const __nv_bfloat16* __restrict__ Al,
    const __nv_bfloat16* __restrict__ Bh_base, const __nv_bfloat16* __restrict__ Bl_base,
    __nv_bfloat16* H0, __nv_bfloat16* L0,
    __nv_bfloat16* H1, __nv_bfloat16* L1,
    __nv_bfloat16* H2, __nv_bfloat16* L2,
    float* __restrict__ Cf, const float* __restrict__ bias)
{
    extern __shared__ __align__(1024) char sm[];
    const int tid = threadIdx.x;
    const int wid = tid >> 5;
    const int lane = tid & 31;
    const int z = blockIdx.z;
    const int colBase = blockIdx.x * 128;
    const int rowBase = blockIdx.y * 256;
    const int wm = (wid & 3) * 64;   // warp M offset (0..192)
    const int wn = (wid >> 2) * 64;  // warp N offset (0 or 64)

    const __nv_bfloat16* Bh = Bh_base + (size_t)z * DM * DM;
    const __nv_bfloat16* Bl = Bl_base + (size_t)z * DM * DM;

    const uint32_t sbase = smem_u32(sm);
    const __nv_bfloat16* agh = Ah + (size_t)rowBase * DM;
    const __nv_bfloat16* agl = Al + (size_t)rowBase * DM;
    const __nv_bfloat16* bgh = Bh + (size_t)colBase * DM;
    const __nv_bfloat16* bgl = Bl + (size_t)colBase * DM;

    float acc[4][8][4];
#pragma unroll
    for (int mi = 0; mi < 4; mi++)
#pragma unroll
        for (int nj = 0; nj < 8; nj++)
#pragma unroll
            for (int r = 0; r < 4; r++) acc[mi][nj][r] = 0.f;

    // hoisted swizzled address bases
    const int lrow = lane & 15;
    const int lquad = (lane >> 4) << 4;
    const uint32_t swz = (uint32_t)((lrow & 7) << 4);
    uint32_t koff[4], arow[4], brow[4];
#pragma unroll
    for (int ks = 0; ks < 4; ks++) koff[ks] = ((uint32_t)(ks * 32 + lquad)) ^ swz;
#pragma unroll
    for (int i = 0; i < 4; i++) {
        arow[i] = (uint32_t)((wm + i * 16 + lrow) * 128);
        brow[i] = (uint32_t)((wn + i * 16 + lrow) * 128);
    }

    {
        load_tile_cp(sbase,          agh, tid, 8);
        load_tile_cp(sbase + OFF_AL, agl, tid, 8);
        load_tile_cp(sbase + OFF_BH, bgh, tid, 4);
        load_tile_cp(sbase + OFF_BL, bgl, tid, 4);
        CP_COMMIT();
    }

    const int NCHUNK = DM / 64;  // 16

    for (int c = 0; c < NCHUNK; c++) {
        CP_WAIT0();
        __syncthreads();
        const uint32_t cur = sbase + (uint32_t)(c & 1) * STAGE_B;

        if (c + 1 < NCHUNK) {
            const uint32_t nst = sbase + (uint32_t)((c + 1) & 1) * STAGE_B;
            const int k0 = (c + 1) * 64;
            load_tile_cp(nst,          agh + k0, tid, 8);
            load_tile_cp(nst + OFF_AL, agl + k0, tid, 8);
            load_tile_cp(nst + OFF_BH, bgh + k0, tid, 4);
            load_tile_cp(nst + OFF_BL, bgl + k0, tid, 4);
            CP_COMMIT();
        }

#pragma unroll
        for (int ks = 0; ks < 4; ks++) {
            const uint32_t ko = koff[ks];
            uint32_t ah[4][4], al[4][4];
#pragma unroll
            for (int mi = 0; mi < 4; mi++) {
                ldsm4(ah[mi], cur + arow[mi] + ko);
                ldsm4(al[mi], cur + OFF_AL + arow[mi] + ko);
            }
#pragma unroll
            for (int ni = 0; ni < 4; ni++) {
                uint32_t bh[4], bl[4];
                ldsm4(bh, cur + OFF_BH + brow[ni] + ko);
                ldsm4(bl, cur + OFF_BL + brow[ni] + ko);
#pragma unroll
                for (int mi = 0; mi < 4; mi++) {
#pragma unroll
                    for (int s = 0; s < 2; s++) {
                        float* a = acc[mi][ni * 2 + s];
                        mma16816(a, ah[mi], bh[s], bh[s + 2]);
                        mma16816(a, ah[mi], bl[s], bl[s + 2]);
                        mma16816(a, al[mi], bh[s], bh[s + 2]);
                    }
                }
            }
        }
        __syncthreads();
    }

    // ---- epilogue ----
    if (SPLIT) {
        __nv_bfloat16* H = (z == 0) ? H0 : (z == 1) ? H1 : H2;
        __nv_bfloat16* L = (z == 0) ? L0 : (z == 1) ? L1 : L2;
        const float sc = (z == 0) ? QSCALE : 1.0f;
#pragma unroll
        for (int mi = 0; mi < 4; mi++) {
            const int r0 = rowBase + wm + mi * 16 + (lane >> 2);
#pragma unroll
            for (int nj = 0; nj < 8; nj++) {
                const int col = colBase + wn + nj * 8 + (lane & 3) * 2;
                uint32_t h0, l0, h1, l1;
                split2(acc[mi][nj][0] * sc, acc[mi][nj][1] * sc, h0, l0);
                split2(acc[mi][nj][2] * sc, acc[mi][nj][3] * sc, h1, l1);
                *(uint32_t*)(H + (size_t)r0 * DM + col) = h0;
                *(uint32_t*)(L + (size_t)r0 * DM + col) = l0;
                *(uint32_t*)(H + (size_t)(r0 + 8) * DM + col) = h1;
                *(uint32_t*)(L + (size_t)(r0 + 8) * DM + col) = l1;
            }
        }
    } else {
#pragma unroll
        for (int mi = 0; mi < 4; mi++) {
            const int r0 = rowBase + wm + mi * 16 + (lane >> 2);
#pragma unroll
            for (int nj = 0; nj < 8; nj++) {
                const int col = colBase + wn + nj * 8 + (lane & 3) * 2;
                float2 bb = *(const float2*)(bias + col);
                float2 v0 = make_float2(acc[mi][nj][0] + bb.x, acc[mi][nj][1] + bb.y);
                float2 v1 = make_float2(acc[mi][nj][2] + bb.x, acc[mi][nj][3] + bb.y);
                *(float2*)(Cf + (size_t)r0 * DM + col) = v0;
                *(float2*)(Cf + (size_t)(r0 + 8) * DM + col) = v1;
            }
        }
    }
}

// ---------------- HMMA causal flash attention ----------------
// Block: 256 thr (8 warps), 128 queries x 64-key tiles, one (b,h) per block.y.
// S = QhKh + QhKl + QlKh; softmax via FFMA exp2 poly; O += PhVh + PhVl + PlVh.
// SMEM: 2 stages x (Kh|Kl|Vh|Vl, each 64x64 bf16 SW128) = 64KB.
#define AT_STAGE 32768
#define AT_SMEM  (2 * AT_STAGE)

__device__ __forceinline__ void load_kv_tiles(
    uint32_t sdst, const __nv_bfloat16* kh, const __nv_bfloat16* kl,
    const __nv_bfloat16* vh, const __nv_bfloat16* vl, int tid)
{
#pragma unroll
    for (int i = 0; i < 2; i++) {
        int f = i * 256 + tid;
        int r = f >> 3;
        int q = f & 7;
        uint32_t byte = (uint32_t)(r * 128 + q * 16);
        byte ^= ((byte >> 3) & 0x70);
        size_t go = (size_t)r * DM + q * 8;
        CP16(sdst + byte,         kh + go);
        CP16(sdst + 8192 + byte,  kl + go);
        CP16(sdst + 16384 + byte, vh + go);
        CP16(sdst + 24576 + byte, vl + go);
    }
}

__global__ __launch_bounds__(256, 1) void attn_mma_kernel(
    const __nv_bfloat16* __restrict__ Qh, const __nv_bfloat16* __restrict__ Ql,
    const __nv_bfloat16* __restrict__ Kh, const __nv_bfloat16* __restrict__ Kl,
    const __nv_bfloat16* __restrict__ Vh, const __nv_bfloat16* __restrict__ Vl,
    __nv_bfloat16* __restrict__ Ch, __nv_bfloat16* __restrict__ Cl)
{
    extern __shared__ __align__(1024) char sm[];
    const uint32_t sb = smem_u32(sm);
    const int tid = threadIdx.x;
    const int wid = tid >> 5;
    const int lane = tid & 31;
    const int mblk = (int)gridDim.x - 1 - (int)blockIdx.x;  // heavy-first
    const int bh = blockIdx.y;
    const int b = bh >> 4;
    const int h = bh & 15;
    const size_t headoff = (size_t)(b * Sq) * DM + h * HDv;
    const int wrow = wid * 16;
    const int lrow = lane & 15;
    const int lq = (lane >> 4) * 16;

    // hoisted swizzled address pieces
    const uint32_t swz = (uint32_t)((lrow & 7) << 4);
    uint32_t koff[4], rowb[4];
#pragma unroll
    for (int j = 0; j < 4; j++) {
        koff[j] = ((uint32_t)(j * 32 + lq)) ^ swz;
        rowb[j] = (uint32_t)((j * 16 + lrow) * 128);
    }

    // ---- prologue: stage Q tile (128x64 hi+lo), ldmatrix into regs ----
    const __nv_bfloat16* qgh = Qh + headoff + (size_t)(mblk * 128) * DM;
    const __nv_bfloat16* qgl = Ql + headoff + (size_t)(mblk * 128) * DM;
#pragma unroll
    for (int i = 0; i < 4; i++) {
        int f = i * 256 + tid;
        int r = f >> 3;
        int q = f & 7;
        uint32_t byte = (uint32_t)(r * 128 + q * 16);
        byte ^= ((byte >> 3) & 0x70);
        size_t go = (size_t)r * DM + q * 8;
        CP16(sb + byte, qgh + go);
        CP16(sb + 16384 + byte, qgl + go);
    }
    CP_COMMIT();
    CP_WAIT0();
    __syncthreads();

    uint32_t qfh[4][4], qfl[4][4];
    const uint32_t qrow = (uint32_t)((wrow + lrow) * 128);
#pragma unroll
    for (int ks = 0; ks < 4; ks++) {
        ldsm4(qfh[ks], sb + qrow + koff[ks]);
        ldsm4(qfl[ks], sb + 16384 + qrow + koff[ks]);
    }
    __syncthreads();

    // ---- tile 0 KV loads ----
    const __nv_bfloat16* kgh = Kh + headoff;
    const __nv_bfloat16* kgl = Kl + headoff;
    const __nv_bfloat16* vgh = Vh + headoff;
    const __nv_bfloat16* vgl = Vl + headoff;
    load_kv_tiles(sb, kgh, kgl, vgh, vgl, tid);
    CP_COMMIT();

    float Oacc[8][4];
#pragma unroll
    for (int nj = 0; nj < 8; nj++)
#pragma unroll
        for (int r = 0; r < 4; r++) Oacc[nj][r] = 0.f;
    float m0 = -INFINITY, m1 = -INFINITY, l0 = 0.f, l1 = 0.f;

    const int ntiles = 2 * mblk + 2;

    for (int t = 0; t < ntiles; t++) {
        CP_WAIT0();
        __syncthreads();
        const uint32_t cur = sb + (uint32_t)(t & 1) * AT_STAGE;

        if (t + 1 < ntiles) {
            const size_t off = (size_t)((t + 1) * 64) * DM;
            load_kv_tiles(sb + (uint32_t)((t + 1) & 1) * AT_STAGE,
                          kgh + off, kgl + off, vgh + off, vgl + off, tid);
            CP_COMMIT();
        }

        // ---- S = Q K^T (3 split terms) ----
        float S[8][4];
#pragma unroll
        for (int nj = 0; nj < 8; nj++)
#pragma unroll
            for (int r = 0; r < 4; r++) S[nj][r] = 0.f;

#pragma unroll
        for (int ks = 0; ks < 4; ks++) {
            const uint32_t ko = koff[ks];
            uint32_t kf_h[4][4], kf_l[4][4];
#pragma unroll
            for (int ni = 0; ni < 4; ni++) {
                ldsm4(kf_h[ni], cur + rowb[ni] + ko);
                ldsm4(kf_l[ni], cur + 8192 + rowb[ni] + ko);
            }
#pragma unroll
            for (int nj = 0; nj < 8; nj++) {
                const int ni = nj >> 1, s = nj & 1;
                mma16816(S[nj], qfh[ks], kf_h[ni][s], kf_h[ni][s + 2]);
                mma16816(S[nj], qfh[ks], kf_l[ni][s], kf_l[ni][s + 2]);
                mma16816(S[nj], qfl[ks], kf_h[ni][s], kf_h[ni][s + 2]);
            }
        }

        // ---- causal mask (last two tiles only) ----
        if (t >= ntiles - 2) {
            const int rg0 = mblk * 128 + wrow + (lane >> 2);
            const int rg1 = rg0 + 8;
            const int cb = t * 64 + (lane & 3) * 2;
#pragma unroll
            for (int nj = 0; nj < 8; nj++) {
                const int c0 = cb + nj * 8, c1 = c0 + 1;
                if (c0 > rg0) S[nj][0] = -1e30f;
                if (c1 > rg0) S[nj][1] = -1e30f;
                if (c0 > rg1) S[nj][2] = -1e30f;
                if (c1 > rg1) S[nj][3] = -1e30f;
            }
        }

        // ---- online softmax (exp2 poly on FFMA pipe) ----
        float mt0 = -INFINITY, mt1 = -INFINITY;
#pragma unroll
        for (int nj = 0; nj < 8; nj++) {
            mt0 = fmaxf(mt0, fmaxf(S[nj][0], S[nj][1]));
            mt1 = fmaxf(mt1, fmaxf(S[nj][2], S[nj][3]));
        }
        mt0 = fmaxf(mt0, __shfl_xor_sync(0xffffffffu, mt0, 1));
        mt0 = fmaxf(mt0, __shfl_xor_sync(0xffffffffu, mt0, 2));
        mt1 = fmaxf(mt1, __shfl_xor_sync(0xffffffffu, mt1, 1));
        mt1 = fmaxf(mt1, __shfl_xor_sync(0xffffffffu, mt1, 2));
        const float mn0 = fmaxf(m0, mt0), mn1 = fmaxf(m1, mt1);
        const float a0 = exp2p(m0 - mn0), a1 = exp2p(m1 - mn1);
        m0 = mn0; m1 = mn1;
        l0 *= a0; l1 *= a1;
        float rs0 = 0.f, rs1 = 0.f;
#pragma unroll
        for (int nj = 0; nj < 8; nj++) {
            Oacc[nj][0] *= a0; Oacc[nj][1] *= a0;
            Oacc[nj][2] *= a1; Oacc[nj][3] *= a1;
            S[nj][0] = exp2p(S[nj][0] - mn0);
            S[nj][1] = exp2p(S[nj][1] - mn0);
            S[nj][2] = exp2p(S[nj][2] - mn1);
            S[nj][3] = exp2p(S[nj][3] - mn1);
            rs0 += S[nj][0] + S[nj][1];
            rs1 += S[nj][2] + S[nj][3];
        }
        l0 += rs0; l1 += rs1;

        // ---- O += P V (3 split terms; V^T via ldmatrix.trans) ----
#pragma unroll
        for (int kk = 0; kk < 4; kk++) {
            uint32_t pah[4], pal[4];
            split2(S[2 * kk][0],     S[2 * kk][1],     pah[0], pal[0]);
            split2(S[2 * kk][2],     S[2 * kk][3],     pah[1], pal[1]);
            split2(S[2 * kk + 1][0], S[2 * kk + 1][1], pah[2], pal[2]);
            split2(S[2 * kk + 1][2], S[2 * kk + 1][3], pah[3], pal[3]);
#pragma unroll
            for (int dp = 0; dp < 4; dp++) {
                const uint32_t vb = cur + rowb[kk] + koff[dp];
                uint32_t vfh[4], vfl[4];
                ldsm4t(vfh, vb + 16384);
                ldsm4t(vfl, vb + 24576);
                mma16816(Oacc[2 * dp], pah, vfh[0], vfh[1]);
                mma16816(Oacc[2 * dp], pah, vfl[0], vfl[1]);
                mma16816(Oacc[2 * dp], pal, vfh[0], vfh[1]);
                mma16816(Oacc[2 * dp + 1], pah, vfh[2], vfh[3]);
                mma16816(Oacc[2 * dp + 1], pah, vfl[2], vfl[3]);
                mma16816(Oacc[2 * dp + 1], pal, vfh[2], vfh[3]);
            }
        }
    }

    // ---- epilogue ----
    l0 += __shfl_xor_sync(0xffffffffu, l0, 1);
    l0 += __shfl_xor_sync(0xffffffffu, l0, 2);
    l1 += __shfl_xor_sync(0xffffffffu, l1, 1);
    l1 += __shfl_xor_sync(0xffffffffu, l1, 2);
    const float inv0 = 1.f / l0, inv1 = 1.f / l1;
    const size_t tok0 = (size_t)(b * Sq + mblk * 128 + wrow + (lane >> 2));
    const size_t tok1 = tok0 + 8;
    const int colb = h * HDv + (lane & 3) * 2;
#pragma unroll
    for (int nj = 0; nj < 8; nj++) {
        const int col = colb + nj * 8;
        uint32_t h0, lo0, h1, lo1;
        split2(Oacc[nj][0] * inv0, Oacc[nj][1] * inv0, h0, lo0);
        split2(Oacc[nj][2] * inv1, Oacc[nj][3] * inv1, h1, lo1);
        *(uint32_t*)(Ch + tok0 * DM + col) = h0;
        *(uint32_t*)(Cl + tok0 * DM + col) = lo0;
        *(uint32_t*)(Ch + tok1 * DM + col) = h1;
        *(uint32_t*)(Cl + tok1 * DM + col) = lo1;
    }
}

// ---------------------------------------------------------------------------
extern "C" void kernel_launch(void* const* d_in, const int* in_sizes, int n_in,
                              void* d_out, int out_size)
{
    const float* x  = (const float*)d_in[0];
    const float* Wq = (const float*)d_in[1];
    const float* Wk = (const float*)d_in[2];
    const float* Wv = (const float*)d_in[3];
    const float* Wo = (const float*)d_in[4];
    const float* bo = (const float*)d_in[5];
    float* out = (float*)d_out;

    __nv_bfloat16 *xh, *xl, *qh, *ql, *kh, *kl, *vh, *vl, *ch, *cl, *wth, *wtl;
    cudaGetSymbolAddress((void**)&xh, g_xh);
    cudaGetSymbolAddress((void**)&xl, g_xl);
    cudaGetSymbolAddress((void**)&qh, g_qh);
    cudaGetSymbolAddress((void**)&ql, g_ql);
    cudaGetSymbolAddress((void**)&kh, g_kh);
    cudaGetSymbolAddress((void**)&kl, g_kl);
    cudaGetSymbolAddress((void**)&vh, g_vh);
    cudaGetSymbolAddress((void**)&vl, g_vl);
    cudaGetSymbolAddress((void**)&ch, g_ch);
    cudaGetSymbolAddress((void**)&cl, g_cl);
    cudaGetSymbolAddress((void**)&wth, g_wth);
    cudaGetSymbolAddress((void**)&wtl, g_wtl);

    static int attr_set = 0;
    if (!attr_set) {
        cudaFuncSetAttribute(gemm_hmma_kernel<true>,
                             cudaFuncAttributeMaxDynamicSharedMemorySize, GEMM_SMEM);
        cudaFuncSetAttribute(gemm_hmma_kernel<false>,
                             cudaFuncAttributeMaxDynamicSharedMemorySize, GEMM_SMEM);
        cudaFuncSetAttribute(attn_mma_kernel,
                             cudaFuncAttributeMaxDynamicSharedMemorySize, AT_SMEM);
        attr_set = 1;
    }

    const int n4 = Mrows * DM / 4;
    fsplit_kernel<<<(n4 + 255) / 256, 256>>>(x, xh, xl, n4);
    wsplit_kernel<<<dim3(32, 32, 4), 256>>>(Wq, Wk, Wv, Wo, wth, wtl);

    // QKV projections -> split bf16 outputs (Q pre-scaled by 0.125*log2e)
    gemm_hmma_kernel<true><<<dim3(DM / 128, Mrows / 256, 3), 256, GEMM_SMEM>>>(
        xh, xl, wth, wtl, qh, ql, kh, kl, vh, vl, nullptr, nullptr);

    attn_mma_kernel<<<dim3(Sq / 128, Bsz * Hh), 256, AT_SMEM>>>(
        qh, ql, kh, kl, vh, vl, ch, cl);

    // output projection (+bias)
    gemm_hmma_kernel<false><<<dim3(DM / 128, Mrows / 256, 1), 256, GEMM_SMEM>>>(
        ch, cl, wth + (size_t)3 * DM * DM, wtl + (size_t)3 * DM * DM,
        nullptr, nullptr, nullptr, nullptr, nullptr, nullptr, out, bo);
}